// round 8
// baseline (speedup 1.0000x reference)
#include <cuda_runtime.h>
#include <cuda_bf16.h>
#include <math.h>
#include <stdint.h>

#define QLEN  2048
#define BSZ   2
#define NH    16
#define DH    64
#define DM    1024
#define KLEN  2048
#define RLEN  2048
// 0.125 * log2(e): scores stored in base-2 domain so softmax uses 2^x
#define SCALE_L2E 0.1803368801111244f

// ---------------- scratch (device globals) ----------------------------------
__device__ float g_Qb[(size_t)BSZ * NH * QLEN * DH];   // Q + r_r_bias, (b,n,q,d)
__device__ float g_K [(size_t)BSZ * NH * KLEN * DH];   // (b,n,k,d)
__device__ float g_V [(size_t)BSZ * NH * KLEN * DH];   // (b,n,k,d)
__device__ float g_Rk[(size_t)NH * RLEN * DH];         // (n,r,d)
__device__ float g_BD[(size_t)BSZ * NH * QLEN * RLEN]; // SHIFTED BD (b,n,q,k)
__device__ float g_AV[(size_t)QLEN * BSZ * DM];        // attn_vec (q,b,n*d)
__device__ float g_negmask[(size_t)BSZ * KLEN];        // 0 or -inf, [b][k]
__device__ float2 g_part[(size_t)BSZ * NH * QLEN * 16]; // per (z,row) x 16 ktiles: (max, sumexp)

// ---------------- helpers -----------------------------------------------------
__device__ __forceinline__ uint32_t f2tf(float f) {
    uint32_t u; asm("cvt.rna.tf32.f32 %0, %1;" : "=r"(u) : "f"(f)); return u;
}
__device__ __forceinline__ void mma8(float* c, const uint32_t* a, const uint32_t* b) {
    asm volatile(
        "mma.sync.aligned.m16n8k8.row.col.f32.tf32.tf32.f32 "
        "{%0,%1,%2,%3}, {%4,%5,%6,%7}, {%8,%9}, {%0,%1,%2,%3};"
        : "+f"(c[0]), "+f"(c[1]), "+f"(c[2]), "+f"(c[3])
        : "r"(a[0]), "r"(a[1]), "r"(a[2]), "r"(a[3]), "r"(b[0]), "r"(b[1]));
}
// raw BD (qi, r) -> shifted slot (validated)
__device__ __forceinline__ void bd_scatter(float* BDz, int qi, int r, float v) {
    if (r >= 2047 - qi)      BDz[(size_t)qi * RLEN + (r - 2047 + qi)] = v;
    else if (qi > 0)         BDz[(size_t)(qi - 1) * RLEN + (r + qi + 1)] = v;
}
// branch-free 2^t on FMA/ALU pipes. t <= 0 expected; -inf/NaN -> clamp -126.
__device__ __forceinline__ float fexp2(float t) {
    t = fmaxf(t, -126.0f);
    float u = t + 12582912.0f;
    int ki = __float_as_int(u) - 0x4B400000;
    float fk = u - 12582912.0f;
    float f = t - fk;
    float p = 0.0013333558f;
    p = fmaf(p, f, 0.0096181291f);
    p = fmaf(p, f, 0.0555041087f);
    p = fmaf(p, f, 0.2402265069f);
    p = fmaf(p, f, 0.6931471806f);
    p = fmaf(p, f, 1.0f);
    return __int_as_float(__float_as_int(p) + (ki << 23));
}

// ---------------- mask detect + expand (validated) ---------------------------
__global__ void mask_expand_kernel(const unsigned char* __restrict__ m) {
    __shared__ int cnt[4];
    __shared__ int smode;
    if (threadIdx.x < 4) cnt[threadIdx.x] = 0;
    __syncthreads();
    for (int i = threadIdx.x; i < 4096; i += blockDim.x)
        if (m[i]) atomicAdd(&cnt[i & 3], 1);
    __syncthreads();
    if (threadIdx.x == 0) {
        int mode;
        if (cnt[1] == 0 && cnt[2] == 0 && cnt[3] == 0) mode = 0;      // int32
        else if (cnt[0] == 0 && cnt[1] == 0)           mode = 1;      // float32
        else                                           mode = 2;      // bool byte
        smode = mode;
    }
    __syncthreads();
    int mode = smode;
    for (int idx = threadIdx.x; idx < KLEN * BSZ; idx += blockDim.x) {
        bool msk;
        if (mode == 0)      msk = ((const int*)m)[idx] != 0;
        else if (mode == 1) msk = ((const float*)m)[idx] != 0.0f;
        else                msk = m[idx] != 0;
        int k = idx >> 1, b = idx & 1;
        g_negmask[b * KLEN + k] = msk ? -INFINITY : 0.0f;
    }
}

// =============================================================================
// NN TF32 MMA GEMM body (validated round 6)
// =============================================================================
#define NN_TF32_BODY(Aptr, Bptr, Kdim, Ndim, ...)                               \
    __shared__ uint32_t As[128][36];                                            \
    __shared__ uint32_t Bs[32][136];                                            \
    int tid = threadIdx.x;                                                      \
    int row0 = blockIdx.y * 128, col0 = blockIdx.x * 128;                       \
    int wid = tid >> 5, lane = tid & 31, g = lane >> 2, t = lane & 3;           \
    int wm = (wid & 3) * 32, wn = (wid >> 2) * 64;                              \
    (void)lane;                                                                 \
    float c[2][8][4] = {};                                                      \
    float4 pa[4], pb[4];                                                        \
    _Pragma("unroll")                                                           \
    for (int i = 0; i < 4; i++) {                                               \
        int f4 = tid + i * 256;                                                 \
        int rw = f4 >> 3, c4 = (f4 & 7) * 4;                                    \
        pa[i] = *(const float4*)&Aptr[(size_t)(row0 + rw) * Kdim + c4];         \
        int brw = f4 >> 5, bc4 = (f4 & 31) * 4;                                 \
        pb[i] = *(const float4*)&Bptr[(size_t)brw * Ndim + col0 + bc4];         \
    }                                                                           \
    for (int k0c = 0; k0c < Kdim; k0c += 32) {                                  \
        _Pragma("unroll")                                                       \
        for (int i = 0; i < 4; i++) {                                           \
            int f4 = tid + i * 256;                                             \
            int rw = f4 >> 3, c4 = (f4 & 7) * 4;                                \
            *(uint4*)&As[rw][c4] =                                              \
                make_uint4(f2tf(pa[i].x), f2tf(pa[i].y), f2tf(pa[i].z), f2tf(pa[i].w)); \
            int brw = f4 >> 5, bc4 = (f4 & 31) * 4;                             \
            *(uint4*)&Bs[brw][bc4] =                                            \
                make_uint4(f2tf(pb[i].x), f2tf(pb[i].y), f2tf(pb[i].z), f2tf(pb[i].w)); \
        }                                                                       \
        __syncthreads();                                                        \
        if (k0c + 32 < Kdim) {                                                  \
            _Pragma("unroll")                                                   \
            for (int i = 0; i < 4; i++) {                                       \
                int f4 = tid + i * 256;                                         \
                int rw = f4 >> 3, c4 = (f4 & 7) * 4;                            \
                pa[i] = *(const float4*)&Aptr[(size_t)(row0 + rw) * Kdim + k0c + 32 + c4]; \
                int brw = f4 >> 5, bc4 = (f4 & 31) * 4;                         \
                pb[i] = *(const float4*)&Bptr[(size_t)(k0c + 32 + brw) * Ndim + col0 + bc4]; \
            }                                                                   \
        }                                                                       \
        _Pragma("unroll")                                                       \
        for (int k0 = 0; k0 < 32; k0 += 8) {                                    \
            uint32_t a[2][4], b2[8][2];                                         \
            _Pragma("unroll")                                                   \
            for (int mt = 0; mt < 2; mt++) {                                    \
                int r = wm + mt * 16 + g;                                       \
                a[mt][0] = As[r][k0 + t];     a[mt][1] = As[r + 8][k0 + t];     \
                a[mt][2] = As[r][k0 + t + 4]; a[mt][3] = As[r + 8][k0 + t + 4]; \
            }                                                                   \
            _Pragma("unroll")                                                   \
            for (int nt = 0; nt < 8; nt++) {                                    \
                int cn = wn + nt * 8 + g;                                       \
                b2[nt][0] = Bs[k0 + t][cn];                                     \
                b2[nt][1] = Bs[k0 + t + 4][cn];                                 \
            }                                                                   \
            _Pragma("unroll")                                                   \
            for (int mt = 0; mt < 2; mt++)                                      \
                _Pragma("unroll")                                               \
                for (int nt = 0; nt < 8; nt++) mma8(c[mt][nt], a[mt], b2[nt]);  \
        }                                                                       \
        __syncthreads();                                                        \
    }                                                                           \
    __VA_ARGS__

// ---------------- GEMM 1: heads = w @ qkv_w -> Qb/K/V (TF32) -----------------
__global__ __launch_bounds__(256)
void gemm_qkv_kernel(const float* __restrict__ A, const float* __restrict__ B,
                     const float* __restrict__ rbias) {
    NN_TF32_BODY(A, B, 1024, 3072, {
        for (int mt = 0; mt < 2; mt++) {
            for (int rr = 0; rr < 2; rr++) {
                int m = row0 + wm + mt * 16 + g + rr * 8;
                int q = m >> 1;
                int bb = m & 1;
                for (int nt = 0; nt < 8; nt++) {
                    int cc = col0 + wn + nt * 8 + 2 * t;
                    int sec = cc >> 10;
                    int h = (cc & 1023) >> 6;
                    int d = cc & 63;
                    size_t off = ((size_t)(bb * NH + h) * QLEN + q) * DH + d;
                    float vx = c[mt][nt][rr * 2 + 0];
                    float vy = c[mt][nt][rr * 2 + 1];
                    if (sec == 0) {
                        float2 rb = *(const float2*)&rbias[h * 64 + d];
                        float2 v;
                        v.x = vx + rb.x;
                        v.y = vy + rb.y;
                        *(float2*)&g_Qb[off] = v;
                    } else if (sec == 1) {
                        float2 v; v.x = vx; v.y = vy;
                        *(float2*)&g_K[off] = v;
                    } else {
                        float2 v; v.x = vx; v.y = vy;
                        *(float2*)&g_V[off] = v;
                    }
                }
            }
        }
    })
}

// ---------------- GEMM 2: r_head_k = r @ r_net_w -> Rk (TF32) ----------------
__global__ __launch_bounds__(256)
void gemm_rnet_kernel(const float* __restrict__ A, const float* __restrict__ B) {
    NN_TF32_BODY(A, B, 1024, 1024, {
        for (int mt = 0; mt < 2; mt++) {
            for (int rr = 0; rr < 2; rr++) {
                int m = row0 + wm + mt * 16 + g + rr * 8;
                for (int nt = 0; nt < 8; nt++) {
                    int cc = col0 + wn + nt * 8 + 2 * t;
                    int h = cc >> 6;
                    int d = cc & 63;
                    float2 v;
                    v.x = c[mt][nt][rr * 2 + 0];
                    v.y = c[mt][nt][rr * 2 + 1];
                    *(float2*)&g_Rk[((size_t)h * RLEN + m) * DH + d] = v;
                }
            }
        }
    })
}

// ---------------- GEMM 6: output = attn_vec @ o_w (TF32) ---------------------
__global__ __launch_bounds__(256)
void gemm_out_kernel(const float* __restrict__ B, float* __restrict__ out) {
    const float* A = g_AV;
    NN_TF32_BODY(A, B, 1024, 1024, {
        for (int mt = 0; mt < 2; mt++) {
            for (int rr = 0; rr < 2; rr++) {
                int m = row0 + wm + mt * 16 + g + rr * 8;
                for (int nt = 0; nt < 8; nt++) {
                    int cc = col0 + wn + nt * 8 + 2 * t;
                    float2 v;
                    v.x = c[mt][nt][rr * 2 + 0];
                    v.y = c[mt][nt][rr * 2 + 1];
                    *(float2*)&out[(size_t)m * 1024 + cc] = v;
                }
            }
        }
    })
}

// =============================================================================
// TF32 MMA NT kernels
// =============================================================================
#define SMEM_STRIDE 68

// ---------------- BD = Qb @ Rk^T, scattered pre-shifted (validated) ----------
__global__ __launch_bounds__(256)
void bd_mma_kernel() {
    extern __shared__ uint32_t sm[];
    uint32_t (*Qs)[SMEM_STRIDE] = (uint32_t(*)[SMEM_STRIDE])sm;
    uint32_t (*Ks)[SMEM_STRIDE] = (uint32_t(*)[SMEM_STRIDE])(sm + 128 * SMEM_STRIDE);
    int z = blockIdx.z;
    int n = z & (NH - 1);
    const float* Aptr = g_Qb + (size_t)z * QLEN * DH;
    const float* Bptr = g_Rk + (size_t)n * RLEN * DH;
    int row0 = blockIdx.y * 128, col0 = blockIdx.x * 128;
    int tid = threadIdx.x;
#pragma unroll
    for (int i = 0; i < 8; i++) {
        int f4 = tid + i * 256;
        int rw = f4 >> 4, c4 = (f4 & 15) * 4;
        float4 qa = *(const float4*)&Aptr[(size_t)(row0 + rw) * DH + c4];
        float4 kb = *(const float4*)&Bptr[(size_t)(col0 + rw) * DH + c4];
        uint4 qu = make_uint4(f2tf(qa.x), f2tf(qa.y), f2tf(qa.z), f2tf(qa.w));
        uint4 ku = make_uint4(f2tf(kb.x), f2tf(kb.y), f2tf(kb.z), f2tf(kb.w));
        *(uint4*)&Qs[rw][c4] = qu;
        *(uint4*)&Ks[rw][c4] = ku;
    }
    __syncthreads();
    int wid = tid >> 5, lane = tid & 31, g = lane >> 2, t = lane & 3;
    int wm = (wid & 3) * 32, wn = (wid >> 2) * 64;
    float c[2][8][4] = {};
#pragma unroll
    for (int k0 = 0; k0 < 64; k0 += 8) {
        uint32_t a[2][4], b[8][2];
#pragma unroll
        for (int mt = 0; mt < 2; mt++) {
            int r = wm + mt * 16 + g;
            a[mt][0] = Qs[r][k0 + t];     a[mt][1] = Qs[r + 8][k0 + t];
            a[mt][2] = Qs[r][k0 + t + 4]; a[mt][3] = Qs[r + 8][k0 + t + 4];
        }
#pragma unroll
        for (int nt = 0; nt < 8; nt++) {
            int r = wn + nt * 8 + g;
            b[nt][0] = Ks[r][k0 + t];
            b[nt][1] = Ks[r][k0 + t + 4];
        }
#pragma unroll
        for (int mt = 0; mt < 2; mt++)
#pragma unroll
            for (int nt = 0; nt < 8; nt++) mma8(c[mt][nt], a[mt], b[nt]);
    }
    float* BDz = g_BD + (size_t)z * QLEN * RLEN;
#pragma unroll
    for (int mt = 0; mt < 2; mt++) {
        int q0 = row0 + wm + mt * 16 + g;
#pragma unroll
        for (int nt = 0; nt < 8; nt++) {
            int rb = col0 + wn + nt * 8 + 2 * t;
            bd_scatter(BDz, q0,     rb,     c[mt][nt][0]);
            bd_scatter(BDz, q0,     rb + 1, c[mt][nt][1]);
            bd_scatter(BDz, q0 + 8, rb,     c[mt][nt][2]);
            bd_scatter(BDz, q0 + 8, rb + 1, c[mt][nt][3]);
        }
    }
}

// ---------------- scores + per-tile softmax partials -------------------------
// Epilogue: stage AC tile in SMEM (stride 132 floats -> 16B-aligned rows),
// then coalesced float4 pass adding BD + mask, writing scores, and
// warp-reducing per-row (max, sumexp) partials into g_part.
__global__ __launch_bounds__(256)
void score_mma_kernel(float* __restrict__ cov) {
    extern __shared__ uint32_t sm[];
    uint32_t (*Qs)[SMEM_STRIDE] = (uint32_t(*)[SMEM_STRIDE])sm;
    uint32_t (*Ks)[SMEM_STRIDE] = (uint32_t(*)[SMEM_STRIDE])(sm + 128 * SMEM_STRIDE);
    int z = blockIdx.z;
    int b = z >> 4;
    const float* Aptr = g_Qb + (size_t)z * QLEN * DH;
    const float* Bptr = g_K + (size_t)z * KLEN * DH;
    int row0 = blockIdx.y * 128, col0 = blockIdx.x * 128;
    int tid = threadIdx.x;
#pragma unroll
    for (int i = 0; i < 8; i++) {
        int f4 = tid + i * 256;
        int rw = f4 >> 4, c4 = (f4 & 15) * 4;
        float4 qa = *(const float4*)&Aptr[(size_t)(row0 + rw) * DH + c4];
        float4 kb = *(const float4*)&Bptr[(size_t)(col0 + rw) * DH + c4];
        uint4 qu = make_uint4(f2tf(qa.x), f2tf(qa.y), f2tf(qa.z), f2tf(qa.w));
        uint4 ku = make_uint4(f2tf(kb.x), f2tf(kb.y), f2tf(kb.z), f2tf(kb.w));
        *(uint4*)&Qs[rw][c4] = qu;
        *(uint4*)&Ks[rw][c4] = ku;
    }
    __syncthreads();
    int wid = tid >> 5, lane = tid & 31, g = lane >> 2, t = lane & 3;
    int wm = (wid & 3) * 32, wn = (wid >> 2) * 64;
    float c[2][8][4] = {};
#pragma unroll
    for (int k0 = 0; k0 < 64; k0 += 8) {
        uint32_t a[2][4], b2[8][2];
#pragma unroll
        for (int mt = 0; mt < 2; mt++) {
            int r = wm + mt * 16 + g;
            a[mt][0] = Qs[r][k0 + t];     a[mt][1] = Qs[r + 8][k0 + t];
            a[mt][2] = Qs[r][k0 + t + 4]; a[mt][3] = Qs[r + 8][k0 + t + 4];
        }
#pragma unroll
        for (int nt = 0; nt < 8; nt++) {
            int r = wn + nt * 8 + g;
            b2[nt][0] = Ks[r][k0 + t];
            b2[nt][1] = Ks[r][k0 + t + 4];
        }
#pragma unroll
        for (int mt = 0; mt < 2; mt++)
#pragma unroll
            for (int nt = 0; nt < 8; nt++) mma8(c[mt][nt], a[mt], b2[nt]);
    }
    // stage AC into SMEM (Qs/Ks space is free now); stride 132 = 16B-aligned rows
    __syncthreads();
    float* Cs = (float*)sm;              // 128 x 132
#pragma unroll
    for (int mt = 0; mt < 2; mt++)
#pragma unroll
        for (int nt = 0; nt < 8; nt++)
#pragma unroll
            for (int rr = 0; rr < 2; rr++) {
                int r = wm + mt * 16 + g + rr * 8;
                int ccol = wn + nt * 8 + 2 * t;
                Cs[r * 132 + ccol]     = c[mt][nt][rr * 2 + 0];
                Cs[r * 132 + ccol + 1] = c[mt][nt][rr * 2 + 1];
            }
    __syncthreads();
    const float* BDz = g_BD + (size_t)z * QLEN * RLEN;
    const float* neg = g_negmask + (size_t)b * KLEN;
    float* Cz = cov + (size_t)z * QLEN * KLEN;
    float2* partRow = g_part + ((size_t)z * QLEN + blockIdx.y * 128) * 16 + blockIdx.x;
#pragma unroll
    for (int i = 0; i < 16; i++) {
        int rw = wid + 8 * i;            // warp owns full rows
        int q = row0 + rw;
        int kb = col0 + lane * 4;
        float4 ac = *(float4*)&Cs[rw * 132 + lane * 4];
        float4 bd = *(const float4*)&BDz[(size_t)q * RLEN + kb];
        float4 ng = *(const float4*)&neg[kb];
        if (kb     == q + 1) bd.x = 0.0f;
        if (kb + 1 == q + 1) bd.y = 0.0f;
        if (kb + 2 == q + 1) bd.z = 0.0f;
        if (kb + 3 == q + 1) bd.w = 0.0f;
        float4 s;
        s.x = (ac.x + bd.x) * SCALE_L2E + ng.x;
        s.y = (ac.y + bd.y) * SCALE_L2E + ng.y;
        s.z = (ac.z + bd.z) * SCALE_L2E + ng.z;
        s.w = (ac.w + bd.w) * SCALE_L2E + ng.w;
        *(float4*)&Cz[(size_t)q * KLEN + kb] = s;
        float mx = fmaxf(fmaxf(s.x, s.y), fmaxf(s.z, s.w));
#pragma unroll
        for (int o = 16; o; o >>= 1) mx = fmaxf(mx, __shfl_xor_sync(0xffffffffu, mx, o));
        float es = ((fexp2(s.x - mx) + fexp2(s.y - mx)) +
                    (fexp2(s.z - mx) + fexp2(s.w - mx)));
#pragma unroll
        for (int o = 16; o; o >>= 1) es += __shfl_xor_sync(0xffffffffu, es, o);
        if (lane == 0) partRow[(size_t)rw * 16] = make_float2(mx, es);
    }
}

// ---------------- fused softmax + PV (replaces softmax_kernel + pv) ----------
__global__ __launch_bounds__(256)
void pv_mma_kernel(float* __restrict__ cov) {
    extern __shared__ uint32_t sm[];
    uint32_t (*Ps)[SMEM_STRIDE] = (uint32_t(*)[SMEM_STRIDE])sm;
    uint32_t (*Vs)[SMEM_STRIDE] = (uint32_t(*)[SMEM_STRIDE])(sm + 128 * SMEM_STRIDE);
    float* smM   = (float*)(sm + (128 + 64) * SMEM_STRIDE);
    float* smInv = smM + 128;
    int z = blockIdx.y;
    int b = z >> 4, n = z & (NH - 1);
    float* P = cov + (size_t)z * QLEN * KLEN;
    const float* Vm = g_V + (size_t)z * KLEN * DH;
    int row0 = blockIdx.x * 128;
    int tid = threadIdx.x;
    // phase 0: combine 16 per-tile partials -> per-row (max, 1/S)
    if (tid < 128) {
        const float2* pp = g_part + ((size_t)z * QLEN + row0 + tid) * 16;
        float m = -INFINITY;
#pragma unroll
        for (int i = 0; i < 16; i++) m = fmaxf(m, pp[i].x);
        float S = 0.0f;
#pragma unroll
        for (int i = 0; i < 16; i++) S += pp[i].y * fexp2(pp[i].x - m);
        smM[tid] = m;
        smInv[tid] = (m == -INFINITY) ? 0.0f : 1.0f / S;
    }
    __syncthreads();
    int wid = tid >> 5, lane = tid & 31, g = lane >> 2, t = lane & 3;
    int wm = (wid & 3) * 32, wn = (wid >> 2) * 32;
    float c[2][4][4] = {};
    for (int kc = 0; kc < KLEN; kc += 64) {
#pragma unroll
        for (int i = 0; i < 8; i++) {
            int f4 = tid + i * 256;
            int rw = f4 >> 4, c4 = (f4 & 15) * 4;
            float4 v = *(const float4*)&P[(size_t)(row0 + rw) * KLEN + kc + c4];
            float m = smM[rw], is = smInv[rw];
            float4 e;
            e.x = fexp2(v.x - m) * is;
            e.y = fexp2(v.y - m) * is;
            e.z = fexp2(v.z - m) * is;
            e.w = fexp2(v.w - m) * is;
            *(float4*)&P[(size_t)(row0 + rw) * KLEN + kc + c4] = e;   // coverage out
            *(uint4*)&Ps[rw][c4] = make_uint4(f2tf(e.x), f2tf(e.y), f2tf(e.z), f2tf(e.w));
        }
#pragma unroll
        for (int i = 0; i < 4; i++) {
            int f4 = tid + i * 256;
            int rw = f4 >> 4, c4 = (f4 & 15) * 4;
            float4 v = *(const float4*)&Vm[(size_t)(kc + rw) * DH + c4];
            *(uint4*)&Vs[rw][c4] = make_uint4(f2tf(v.x), f2tf(v.y), f2tf(v.z), f2tf(v.w));
        }
        __syncthreads();
#pragma unroll
        for (int k0 = 0; k0 < 64; k0 += 8) {
            uint32_t a[2][4], b2[4][2];
#pragma unroll
            for (int mt = 0; mt < 2; mt++) {
                int r = wm + mt * 16 + g;
                a[mt][0] = Ps[r][k0 + t];     a[mt][1] = Ps[r + 8][k0 + t];
                a[mt][2] = Ps[r][k0 + t + 4]; a[mt][3] = Ps[r + 8][k0 + t + 4];
            }
#pragma unroll
            for (int nt = 0; nt < 4; nt++) {
                int cn = wn + nt * 8 + g;
                b2[nt][0] = Vs[k0 + t][cn];
                b2[nt][1] = Vs[k0 + t + 4][cn];
            }
#pragma unroll
            for (int mt = 0; mt < 2; mt++)
#pragma unroll
                for (int nt = 0; nt < 4; nt++) mma8(c[mt][nt], a[mt], b2[nt]);
        }
        __syncthreads();
    }
#pragma unroll
    for (int mt = 0; mt < 2; mt++) {
        int q0 = row0 + wm + mt * 16 + g;
#pragma unroll
        for (int nt = 0; nt < 4; nt++) {
            int d = wn + nt * 8 + 2 * t;
#pragma unroll
            for (int rr = 0; rr < 2; rr++) {
                int q = q0 + rr * 8;
                float2 v;
                v.x = c[mt][nt][rr * 2 + 0];
                v.y = c[mt][nt][rr * 2 + 1];
                *(float2*)&g_AV[((size_t)q * BSZ + b) * DM + n * DH + d] = v;
            }
        }
    }
}

// ---------------- launch ------------------------------------------------------
extern "C" void kernel_launch(void* const* d_in, const int* in_sizes, int n_in,
                              void* d_out, int out_size) {
    const float* w       = (const float*)d_in[0];
    const float* r       = (const float*)d_in[1];
    const void*  mask    = d_in[2];
    const float* qkv_w   = (const float*)d_in[3];
    const float* r_net_w = (const float*)d_in[4];
    const float* o_w     = (const float*)d_in[5];
    const float* r_r_bias = (const float*)d_in[7];  // reference bug: r_r_bias for both

    float* out = (float*)d_out;
    float* cov = out + (size_t)QLEN * BSZ * DM;

    const int SMEM_NT = 2 * 128 * SMEM_STRIDE * 4;              // 69632 (>= 128*132*4)
    const int SMEM_PV = (128 + 64) * SMEM_STRIDE * 4 + 1024;    // 53248
    static int attr_done = 0;
    if (!attr_done) {
        cudaFuncSetAttribute(bd_mma_kernel,    cudaFuncAttributeMaxDynamicSharedMemorySize, SMEM_NT);
        cudaFuncSetAttribute(score_mma_kernel, cudaFuncAttributeMaxDynamicSharedMemorySize, SMEM_NT);
        cudaFuncSetAttribute(pv_mma_kernel,    cudaFuncAttributeMaxDynamicSharedMemorySize, SMEM_PV);
        attr_done = 1;
    }

    mask_expand_kernel<<<1, 256>>>((const unsigned char*)mask);
    gemm_qkv_kernel<<<dim3(24, 32), 256>>>(w, qkv_w, r_r_bias);
    gemm_rnet_kernel<<<dim3(8, 16), 256>>>(r, r_net_w);
    bd_mma_kernel<<<dim3(16, 16, BSZ * NH), 256, SMEM_NT>>>();
    score_mma_kernel<<<dim3(16, 16, BSZ * NH), 256, SMEM_NT>>>(cov);
    pv_mma_kernel<<<dim3(16, BSZ * NH), 256, SMEM_PV>>>(cov);
    gemm_out_kernel<<<dim3(8, 32), 256>>>(o_w, out);
}

// round 9
// speedup vs baseline: 1.2798x; 1.2798x over previous
#include <cuda_runtime.h>
#include <cuda_bf16.h>
#include <math.h>
#include <stdint.h>

#define QLEN  2048
#define BSZ   2
#define NH    16
#define DH    64
#define DM    1024
#define KLEN  2048
#define RLEN  2048
// 0.125 * log2(e): scores stored in base-2 domain so softmax uses 2^x
#define SCALE_L2E 0.1803368801111244f

// ---------------- scratch (device globals) ----------------------------------
__device__ float g_Qb[(size_t)BSZ * NH * QLEN * DH];   // Q + r_r_bias, (b,n,q,d)
__device__ float g_K [(size_t)BSZ * NH * KLEN * DH];   // (b,n,k,d)
__device__ float g_V [(size_t)BSZ * NH * KLEN * DH];   // (b,n,k,d)
__device__ float g_Rk[(size_t)NH * RLEN * DH];         // (n,r,d)
__device__ float g_BD[(size_t)BSZ * NH * QLEN * RLEN]; // SHIFTED BD (b,n,q,k)
__device__ float g_AV[(size_t)QLEN * BSZ * DM];        // attn_vec (q,b,n*d)
__device__ float g_negmask[(size_t)BSZ * KLEN];        // 0 or -inf, [b][k]

// ---------------- helpers -----------------------------------------------------
__device__ __forceinline__ uint32_t f2tf(float f) {
    uint32_t u; asm("cvt.rna.tf32.f32 %0, %1;" : "=r"(u) : "f"(f)); return u;
}
__device__ __forceinline__ void mma8(float* c, const uint32_t* a, const uint32_t* b) {
    asm volatile(
        "mma.sync.aligned.m16n8k8.row.col.f32.tf32.tf32.f32 "
        "{%0,%1,%2,%3}, {%4,%5,%6,%7}, {%8,%9}, {%0,%1,%2,%3};"
        : "+f"(c[0]), "+f"(c[1]), "+f"(c[2]), "+f"(c[3])
        : "r"(a[0]), "r"(a[1]), "r"(a[2]), "r"(a[3]), "r"(b[0]), "r"(b[1]));
}
// branch-free 2^t on FMA/ALU pipes. t <= 0 expected; -inf -> ~0.
__device__ __forceinline__ float fexp2(float t) {
    t = fmaxf(t, -126.0f);
    float u = t + 12582912.0f;
    int ki = __float_as_int(u) - 0x4B400000;
    float fk = u - 12582912.0f;
    float f = t - fk;
    float p = 0.0013333558f;
    p = fmaf(p, f, 0.0096181291f);
    p = fmaf(p, f, 0.0555041087f);
    p = fmaf(p, f, 0.2402265069f);
    p = fmaf(p, f, 0.6931471806f);
    p = fmaf(p, f, 1.0f);
    return __int_as_float(__float_as_int(p) + (ki << 23));
}

// ---------------- mask detect + expand (validated) ---------------------------
__global__ void mask_expand_kernel(const unsigned char* __restrict__ m) {
    __shared__ int cnt[4];
    __shared__ int smode;
    if (threadIdx.x < 4) cnt[threadIdx.x] = 0;
    __syncthreads();
    for (int i = threadIdx.x; i < 4096; i += blockDim.x)
        if (m[i]) atomicAdd(&cnt[i & 3], 1);
    __syncthreads();
    if (threadIdx.x == 0) {
        int mode;
        if (cnt[1] == 0 && cnt[2] == 0 && cnt[3] == 0) mode = 0;      // int32
        else if (cnt[0] == 0 && cnt[1] == 0)           mode = 1;      // float32
        else                                           mode = 2;      // bool byte
        smode = mode;
    }
    __syncthreads();
    int mode = smode;
    for (int idx = threadIdx.x; idx < KLEN * BSZ; idx += blockDim.x) {
        bool msk;
        if (mode == 0)      msk = ((const int*)m)[idx] != 0;
        else if (mode == 1) msk = ((const float*)m)[idx] != 0.0f;
        else                msk = m[idx] != 0;
        int k = idx >> 1, b = idx & 1;
        g_negmask[b * KLEN + k] = msk ? -INFINITY : 0.0f;
    }
}

// =============================================================================
// NN TF32 MMA GEMM body (validated round 6)
// =============================================================================
#define NN_TF32_BODY(Aptr, Bptr, Kdim, Ndim, ...)                               \
    __shared__ uint32_t As[128][36];                                            \
    __shared__ uint32_t Bs[32][136];                                            \
    int tid = threadIdx.x;                                                      \
    int row0 = blockIdx.y * 128, col0 = blockIdx.x * 128;                       \
    int wid = tid >> 5, lane = tid & 31, g = lane >> 2, t = lane & 3;           \
    int wm = (wid & 3) * 32, wn = (wid >> 2) * 64;                              \
    (void)lane;                                                                 \
    float c[2][8][4] = {};                                                      \
    float4 pa[4], pb[4];                                                        \
    _Pragma("unroll")                                                           \
    for (int i = 0; i < 4; i++) {                                               \
        int f4 = tid + i * 256;                                                 \
        int rw = f4 >> 3, c4 = (f4 & 7) * 4;                                    \
        pa[i] = *(const float4*)&Aptr[(size_t)(row0 + rw) * Kdim + c4];         \
        int brw = f4 >> 5, bc4 = (f4 & 31) * 4;                                 \
        pb[i] = *(const float4*)&Bptr[(size_t)brw * Ndim + col0 + bc4];         \
    }                                                                           \
    for (int k0c = 0; k0c < Kdim; k0c += 32) {                                  \
        _Pragma("unroll")                                                       \
        for (int i = 0; i < 4; i++) {                                           \
            int f4 = tid + i * 256;                                             \
            int rw = f4 >> 3, c4 = (f4 & 7) * 4;                                \
            *(uint4*)&As[rw][c4] =                                              \
                make_uint4(f2tf(pa[i].x), f2tf(pa[i].y), f2tf(pa[i].z), f2tf(pa[i].w)); \
            int brw = f4 >> 5, bc4 = (f4 & 31) * 4;                             \
            *(uint4*)&Bs[brw][bc4] =                                            \
                make_uint4(f2tf(pb[i].x), f2tf(pb[i].y), f2tf(pb[i].z), f2tf(pb[i].w)); \
        }                                                                       \
        __syncthreads();                                                        \
        if (k0c + 32 < Kdim) {                                                  \
            _Pragma("unroll")                                                   \
            for (int i = 0; i < 4; i++) {                                       \
                int f4 = tid + i * 256;                                         \
                int rw = f4 >> 3, c4 = (f4 & 7) * 4;                            \
                pa[i] = *(const float4*)&Aptr[(size_t)(row0 + rw) * Kdim + k0c + 32 + c4]; \
                int brw = f4 >> 5, bc4 = (f4 & 31) * 4;                         \
                pb[i] = *(const float4*)&Bptr[(size_t)(k0c + 32 + brw) * Ndim + col0 + bc4]; \
            }                                                                   \
        }                                                                       \
        _Pragma("unroll")                                                       \
        for (int k0 = 0; k0 < 32; k0 += 8) {                                    \
            uint32_t a[2][4], b2[8][2];                                         \
            _Pragma("unroll")                                                   \
            for (int mt = 0; mt < 2; mt++) {                                    \
                int r = wm + mt * 16 + g;                                       \
                a[mt][0] = As[r][k0 + t];     a[mt][1] = As[r + 8][k0 + t];     \
                a[mt][2] = As[r][k0 + t + 4]; a[mt][3] = As[r + 8][k0 + t + 4]; \
            }                                                                   \
            _Pragma("unroll")                                                   \
            for (int nt = 0; nt < 8; nt++) {                                    \
                int cn = wn + nt * 8 + g;                                       \
                b2[nt][0] = Bs[k0 + t][cn];                                     \
                b2[nt][1] = Bs[k0 + t + 4][cn];                                 \
            }                                                                   \
            _Pragma("unroll")                                                   \
            for (int mt = 0; mt < 2; mt++)                                      \
                _Pragma("unroll")                                               \
                for (int nt = 0; nt < 8; nt++) mma8(c[mt][nt], a[mt], b2[nt]);  \
        }                                                                       \
        __syncthreads();                                                        \
    }                                                                           \
    __VA_ARGS__

// ---------------- GEMM 1: heads = w @ qkv_w -> Qb/K/V (TF32) -----------------
__global__ __launch_bounds__(256)
void gemm_qkv_kernel(const float* __restrict__ A, const float* __restrict__ B,
                     const float* __restrict__ rbias) {
    NN_TF32_BODY(A, B, 1024, 3072, {
        for (int mt = 0; mt < 2; mt++) {
            for (int rr = 0; rr < 2; rr++) {
                int m = row0 + wm + mt * 16 + g + rr * 8;
                int q = m >> 1;
                int bb = m & 1;
                for (int nt = 0; nt < 8; nt++) {
                    int cc = col0 + wn + nt * 8 + 2 * t;
                    int sec = cc >> 10;
                    int h = (cc & 1023) >> 6;
                    int d = cc & 63;
                    size_t off = ((size_t)(bb * NH + h) * QLEN + q) * DH + d;
                    float vx = c[mt][nt][rr * 2 + 0];
                    float vy = c[mt][nt][rr * 2 + 1];
                    if (sec == 0) {
                        float2 rb = *(const float2*)&rbias[h * 64 + d];
                        float2 v;
                        v.x = vx + rb.x;
                        v.y = vy + rb.y;
                        *(float2*)&g_Qb[off] = v;
                    } else if (sec == 1) {
                        float2 v; v.x = vx; v.y = vy;
                        *(float2*)&g_K[off] = v;
                    } else {
                        float2 v; v.x = vx; v.y = vy;
                        *(float2*)&g_V[off] = v;
                    }
                }
            }
        }
    })
}

// ---------------- GEMM 2: r_head_k = r @ r_net_w -> Rk (TF32) ----------------
__global__ __launch_bounds__(256)
void gemm_rnet_kernel(const float* __restrict__ A, const float* __restrict__ B) {
    NN_TF32_BODY(A, B, 1024, 1024, {
        for (int mt = 0; mt < 2; mt++) {
            for (int rr = 0; rr < 2; rr++) {
                int m = row0 + wm + mt * 16 + g + rr * 8;
                for (int nt = 0; nt < 8; nt++) {
                    int cc = col0 + wn + nt * 8 + 2 * t;
                    int h = cc >> 6;
                    int d = cc & 63;
                    float2 v;
                    v.x = c[mt][nt][rr * 2 + 0];
                    v.y = c[mt][nt][rr * 2 + 1];
                    *(float2*)&g_Rk[((size_t)h * RLEN + m) * DH + d] = v;
                }
            }
        }
    })
}

// ---------------- GEMM 6: output = attn_vec @ o_w (TF32) ---------------------
__global__ __launch_bounds__(256)
void gemm_out_kernel(const float* __restrict__ B, float* __restrict__ out) {
    const float* A = g_AV;
    NN_TF32_BODY(A, B, 1024, 1024, {
        for (int mt = 0; mt < 2; mt++) {
            for (int rr = 0; rr < 2; rr++) {
                int m = row0 + wm + mt * 16 + g + rr * 8;
                for (int nt = 0; nt < 8; nt++) {
                    int cc = col0 + wn + nt * 8 + 2 * t;
                    float2 v;
                    v.x = c[mt][nt][rr * 2 + 0];
                    v.y = c[mt][nt][rr * 2 + 1];
                    *(float2*)&out[(size_t)m * 1024 + cc] = v;
                }
            }
        }
    })
}

// =============================================================================
// TF32 MMA NT kernels
// =============================================================================
#define SMEM_STRIDE 68

// ---------------- BD = Qb @ Rk^T, staged + coalesced pre-shifted scatter -----
// Shifted-row structure: for raw row qi, raw cols r map to
//   r >= 2047-qi : row qi,   k = r-2047+qi   (contiguous in r)
//   r <  2047-qi : row qi-1, k = r+qi+1      (contiguous in r; dropped if qi==0)
// Warp-per-row with lane-stride-1 element assignment -> coalesced stores.
__global__ __launch_bounds__(256)
void bd_mma_kernel() {
    extern __shared__ uint32_t sm[];
    uint32_t (*Qs)[SMEM_STRIDE] = (uint32_t(*)[SMEM_STRIDE])sm;
    uint32_t (*Ks)[SMEM_STRIDE] = (uint32_t(*)[SMEM_STRIDE])(sm + 128 * SMEM_STRIDE);
    int z = blockIdx.z;
    int n = z & (NH - 1);
    const float* Aptr = g_Qb + (size_t)z * QLEN * DH;
    const float* Bptr = g_Rk + (size_t)n * RLEN * DH;
    int row0 = blockIdx.y * 128, col0 = blockIdx.x * 128;
    int tid = threadIdx.x;
#pragma unroll
    for (int i = 0; i < 8; i++) {
        int f4 = tid + i * 256;
        int rw = f4 >> 4, c4 = (f4 & 15) * 4;
        float4 qa = *(const float4*)&Aptr[(size_t)(row0 + rw) * DH + c4];
        float4 kb = *(const float4*)&Bptr[(size_t)(col0 + rw) * DH + c4];
        uint4 qu = make_uint4(f2tf(qa.x), f2tf(qa.y), f2tf(qa.z), f2tf(qa.w));
        uint4 ku = make_uint4(f2tf(kb.x), f2tf(kb.y), f2tf(kb.z), f2tf(kb.w));
        *(uint4*)&Qs[rw][c4] = qu;
        *(uint4*)&Ks[rw][c4] = ku;
    }
    __syncthreads();
    int wid = tid >> 5, lane = tid & 31, g = lane >> 2, t = lane & 3;
    int wm = (wid & 3) * 32, wn = (wid >> 2) * 64;
    float c[2][8][4] = {};
#pragma unroll
    for (int k0 = 0; k0 < 64; k0 += 8) {
        uint32_t a[2][4], b[8][2];
#pragma unroll
        for (int mt = 0; mt < 2; mt++) {
            int r = wm + mt * 16 + g;
            a[mt][0] = Qs[r][k0 + t];     a[mt][1] = Qs[r + 8][k0 + t];
            a[mt][2] = Qs[r][k0 + t + 4]; a[mt][3] = Qs[r + 8][k0 + t + 4];
        }
#pragma unroll
        for (int nt = 0; nt < 8; nt++) {
            int r = wn + nt * 8 + g;
            b[nt][0] = Ks[r][k0 + t];
            b[nt][1] = Ks[r][k0 + t + 4];
        }
#pragma unroll
        for (int mt = 0; mt < 2; mt++)
#pragma unroll
            for (int nt = 0; nt < 8; nt++) mma8(c[mt][nt], a[mt], b[nt]);
    }
    // stage C into SMEM (stride 132 floats; 16B-aligned rows; validated r8)
    __syncthreads();
    float* Cs = (float*)sm;              // 128 x 132
#pragma unroll
    for (int mt = 0; mt < 2; mt++)
#pragma unroll
        for (int nt = 0; nt < 8; nt++)
#pragma unroll
            for (int rr = 0; rr < 2; rr++) {
                int r = wm + mt * 16 + g + rr * 8;
                int ccol = wn + nt * 8 + 2 * t;
                Cs[r * 132 + ccol]     = c[mt][nt][rr * 2 + 0];
                Cs[r * 132 + ccol + 1] = c[mt][nt][rr * 2 + 1];
            }
    __syncthreads();
    float* BDz = g_BD + (size_t)z * QLEN * RLEN;
#pragma unroll
    for (int i = 0; i < 16; i++) {
        int rw = wid + 8 * i;            // warp owns a full raw row
        int qi = row0 + rw;
        int boundary = 2047 - qi;
#pragma unroll
        for (int u = 0; u < 4; u++) {
            int j = lane + 32 * u;
            int r = col0 + j;
            float v = Cs[rw * 132 + j];
            if (r >= boundary) {
                BDz[(size_t)qi * RLEN + (r - 2047 + qi)] = v;
            } else if (qi > 0) {
                BDz[(size_t)(qi - 1) * RLEN + (r + qi + 1)] = v;
            }
        }
    }
}

// ---------------- scores = (Q@K^T + BDsh)*scale + negmask (validated r6) -----
__global__ __launch_bounds__(256)
void score_mma_kernel(float* __restrict__ cov) {
    extern __shared__ uint32_t sm[];
    uint32_t (*Qs)[SMEM_STRIDE] = (uint32_t(*)[SMEM_STRIDE])sm;
    uint32_t (*Ks)[SMEM_STRIDE] = (uint32_t(*)[SMEM_STRIDE])(sm + 128 * SMEM_STRIDE);
    int z = blockIdx.z;
    int b = z >> 4;
    const float* Aptr = g_Qb + (size_t)z * QLEN * DH;
    const float* Bptr = g_K + (size_t)z * KLEN * DH;
    int row0 = blockIdx.y * 128, col0 = blockIdx.x * 128;
    int tid = threadIdx.x;
#pragma unroll
    for (int i = 0; i < 8; i++) {
        int f4 = tid + i * 256;
        int rw = f4 >> 4, c4 = (f4 & 15) * 4;
        float4 qa = *(const float4*)&Aptr[(size_t)(row0 + rw) * DH + c4];
        float4 kb = *(const float4*)&Bptr[(size_t)(col0 + rw) * DH + c4];
        uint4 qu = make_uint4(f2tf(qa.x), f2tf(qa.y), f2tf(qa.z), f2tf(qa.w));
        uint4 ku = make_uint4(f2tf(kb.x), f2tf(kb.y), f2tf(kb.z), f2tf(kb.w));
        *(uint4*)&Qs[rw][c4] = qu;
        *(uint4*)&Ks[rw][c4] = ku;
    }
    __syncthreads();
    int wid = tid >> 5, lane = tid & 31, g = lane >> 2, t = lane & 3;
    int wm = (wid & 3) * 32, wn = (wid >> 2) * 64;
    float c[2][8][4] = {};
#pragma unroll
    for (int k0 = 0; k0 < 64; k0 += 8) {
        uint32_t a[2][4], b2[8][2];
#pragma unroll
        for (int mt = 0; mt < 2; mt++) {
            int r = wm + mt * 16 + g;
            a[mt][0] = Qs[r][k0 + t];     a[mt][1] = Qs[r + 8][k0 + t];
            a[mt][2] = Qs[r][k0 + t + 4]; a[mt][3] = Qs[r + 8][k0 + t + 4];
        }
#pragma unroll
        for (int nt = 0; nt < 8; nt++) {
            int r = wn + nt * 8 + g;
            b2[nt][0] = Ks[r][k0 + t];
            b2[nt][1] = Ks[r][k0 + t + 4];
        }
#pragma unroll
        for (int mt = 0; mt < 2; mt++)
#pragma unroll
            for (int nt = 0; nt < 8; nt++) mma8(c[mt][nt], a[mt], b2[nt]);
    }
    const float* BDz = g_BD + (size_t)z * QLEN * RLEN;
    const float* neg = g_negmask + (size_t)b * KLEN;
    float* Cz = cov + (size_t)z * QLEN * KLEN;
#pragma unroll
    for (int mt = 0; mt < 2; mt++) {
        int q0 = row0 + wm + mt * 16 + g;
#pragma unroll
        for (int nt = 0; nt < 8; nt++) {
            int kb = col0 + wn + nt * 8 + 2 * t;
            float2 ng = *(const float2*)&neg[kb];
#pragma unroll
            for (int rr = 0; rr < 2; rr++) {
                int q = q0 + rr * 8;
                float2 bd2 = *(const float2*)&BDz[(size_t)q * RLEN + kb];
                float bdx = (kb     == q + 1) ? 0.0f : bd2.x;
                float bdy = (kb + 1 == q + 1) ? 0.0f : bd2.y;
                float2 s;
                s.x = (c[mt][nt][rr * 2 + 0] + bdx) * SCALE_L2E + ng.x;
                s.y = (c[mt][nt][rr * 2 + 1] + bdy) * SCALE_L2E + ng.y;
                *(float2*)&Cz[(size_t)q * KLEN + kb] = s;
            }
        }
    }
}

// ---------------- softmax over k (validated; base-2 domain) ------------------
__global__ __launch_bounds__(256)
void softmax_kernel(float* __restrict__ cov) {
    size_t row = blockIdx.x;
    float* p = cov + row * KLEN;
    int t = threadIdx.x;
    float4 v0 = ((const float4*)p)[t];
    float4 v1 = ((const float4*)p)[t + 256];
    float m = fmaxf(fmaxf(fmaxf(v0.x, v0.y), fmaxf(v0.z, v0.w)),
                    fmaxf(fmaxf(v1.x, v1.y), fmaxf(v1.z, v1.w)));
    __shared__ float sred[8];
#pragma unroll
    for (int o = 16; o; o >>= 1) m = fmaxf(m, __shfl_xor_sync(0xffffffffu, m, o));
    if ((t & 31) == 0) sred[t >> 5] = m;
    __syncthreads();
    if (t < 8) {
        float x = sred[t];
#pragma unroll
        for (int o = 4; o; o >>= 1) x = fmaxf(x, __shfl_xor_sync(0xffu, x, o));
        if (t == 0) sred[0] = x;
    }
    __syncthreads();
    m = sred[0];
    if (m == -INFINITY) {   // fully-masked row -> 0 per reference
        float4 zz = make_float4(0.f, 0.f, 0.f, 0.f);
        ((float4*)p)[t] = zz;
        ((float4*)p)[t + 256] = zz;
        return;
    }
    float e0x = fexp2(v0.x - m), e0y = fexp2(v0.y - m);
    float e0z = fexp2(v0.z - m), e0w = fexp2(v0.w - m);
    float e1x = fexp2(v1.x - m), e1y = fexp2(v1.y - m);
    float e1z = fexp2(v1.z - m), e1w = fexp2(v1.w - m);
    float s = (e0x + e0y) + (e0z + e0w) + (e1x + e1y) + (e1z + e1w);
    __shared__ float ssum[8];
#pragma unroll
    for (int o = 16; o; o >>= 1) s += __shfl_xor_sync(0xffffffffu, s, o);
    if ((t & 31) == 0) ssum[t >> 5] = s;
    __syncthreads();
    if (t < 8) {
        float x = ssum[t];
#pragma unroll
        for (int o = 4; o; o >>= 1) x += __shfl_xor_sync(0xffu, x, o);
        if (t == 0) ssum[0] = x;
    }
    __syncthreads();
    float inv = 1.0f / ssum[0];
    ((float4*)p)[t]       = make_float4(e0x * inv, e0y * inv, e0z * inv, e0w * inv);
    ((float4*)p)[t + 256] = make_float4(e1x * inv, e1y * inv, e1z * inv, e1w * inv);
}

// ---------------- PV: attn_vec = P @ V (TF32 MMA, validated r6) --------------
__global__ __launch_bounds__(256)
void pv_mma_kernel(const float* __restrict__ cov) {
    extern __shared__ uint32_t sm[];
    uint32_t (*Ps)[SMEM_STRIDE] = (uint32_t(*)[SMEM_STRIDE])sm;
    uint32_t (*Vs)[SMEM_STRIDE] = (uint32_t(*)[SMEM_STRIDE])(sm + 128 * SMEM_STRIDE);
    int z = blockIdx.y;
    int b = z >> 4, n = z & (NH - 1);
    const float* P = cov + (size_t)z * QLEN * KLEN;
    const float* Vm = g_V + (size_t)z * KLEN * DH;
    int row0 = blockIdx.x * 128;
    int tid = threadIdx.x;
    int wid = tid >> 5, lane = tid & 31, g = lane >> 2, t = lane & 3;
    int wm = (wid & 3) * 32, wn = (wid >> 2) * 32;
    float c[2][4][4] = {};
    for (int kc = 0; kc < KLEN; kc += 64) {
#pragma unroll
        for (int i = 0; i < 8; i++) {
            int f4 = tid + i * 256;
            int rw = f4 >> 4, c4 = (f4 & 15) * 4;
            float4 v = *(const float4*)&P[(size_t)(row0 + rw) * KLEN + kc + c4];
            *(uint4*)&Ps[rw][c4] = make_uint4(f2tf(v.x), f2tf(v.y), f2tf(v.z), f2tf(v.w));
        }
#pragma unroll
        for (int i = 0; i < 4; i++) {
            int f4 = tid + i * 256;
            int rw = f4 >> 4, c4 = (f4 & 15) * 4;
            float4 v = *(const float4*)&Vm[(size_t)(kc + rw) * DH + c4];
            *(uint4*)&Vs[rw][c4] = make_uint4(f2tf(v.x), f2tf(v.y), f2tf(v.z), f2tf(v.w));
        }
        __syncthreads();
#pragma unroll
        for (int k0 = 0; k0 < 64; k0 += 8) {
            uint32_t a[2][4], b2[4][2];
#pragma unroll
            for (int mt = 0; mt < 2; mt++) {
                int r = wm + mt * 16 + g;
                a[mt][0] = Ps[r][k0 + t];     a[mt][1] = Ps[r + 8][k0 + t];
                a[mt][2] = Ps[r][k0 + t + 4]; a[mt][3] = Ps[r + 8][k0 + t + 4];
            }
#pragma unroll
            for (int nt = 0; nt < 4; nt++) {
                int cn = wn + nt * 8 + g;
                b2[nt][0] = Vs[k0 + t][cn];
                b2[nt][1] = Vs[k0 + t + 4][cn];
            }
#pragma unroll
            for (int mt = 0; mt < 2; mt++)
#pragma unroll
                for (int nt = 0; nt < 4; nt++) mma8(c[mt][nt], a[mt], b2[nt]);
        }
        __syncthreads();
    }
#pragma unroll
    for (int mt = 0; mt < 2; mt++) {
        int q0 = row0 + wm + mt * 16 + g;
#pragma unroll
        for (int nt = 0; nt < 4; nt++) {
            int d = wn + nt * 8 + 2 * t;
#pragma unroll
            for (int rr = 0; rr < 2; rr++) {
                int q = q0 + rr * 8;
                float2 v;
                v.x = c[mt][nt][rr * 2 + 0];
                v.y = c[mt][nt][rr * 2 + 1];
                *(float2*)&g_AV[((size_t)q * BSZ + b) * DM + n * DH + d] = v;
            }
        }
    }
}

// ---------------- launch ------------------------------------------------------
extern "C" void kernel_launch(void* const* d_in, const int* in_sizes, int n_in,
                              void* d_out, int out_size) {
    const float* w       = (const float*)d_in[0];
    const float* r       = (const float*)d_in[1];
    const void*  mask    = d_in[2];
    const float* qkv_w   = (const float*)d_in[3];
    const float* r_net_w = (const float*)d_in[4];
    const float* o_w     = (const float*)d_in[5];
    const float* r_r_bias = (const float*)d_in[7];  // reference bug: r_r_bias for both

    float* out = (float*)d_out;
    float* cov = out + (size_t)QLEN * BSZ * DM;

    const int SMEM_NT = 2 * 128 * SMEM_STRIDE * 4;          // 69632 (>= 128*132*4)
    const int SMEM_PV = (128 + 64) * SMEM_STRIDE * 4;       // 52224
    static int attr_done = 0;
    if (!attr_done) {
        cudaFuncSetAttribute(bd_mma_kernel,    cudaFuncAttributeMaxDynamicSharedMemorySize, SMEM_NT);
        cudaFuncSetAttribute(score_mma_kernel, cudaFuncAttributeMaxDynamicSharedMemorySize, SMEM_NT);
        cudaFuncSetAttribute(pv_mma_kernel,    cudaFuncAttributeMaxDynamicSharedMemorySize, SMEM_PV);
        attr_done = 1;
    }

    mask_expand_kernel<<<1, 256>>>((const unsigned char*)mask);
    gemm_qkv_kernel<<<dim3(24, 32), 256>>>(w, qkv_w, r_r_bias);
    gemm_rnet_kernel<<<dim3(8, 16), 256>>>(r, r_net_w);
    bd_mma_kernel<<<dim3(16, 16, BSZ * NH), 256, SMEM_NT>>>();
    score_mma_kernel<<<dim3(16, 16, BSZ * NH), 256, SMEM_NT>>>(cov);
    softmax_kernel<<<BSZ * NH * QLEN, 256>>>(cov);
    pv_mma_kernel<<<dim3(16, BSZ * NH), 256, SMEM_PV>>>(cov);
    gemm_out_kernel<<<dim3(8, 32), 256>>>(o_w, out);
}

// round 10
// speedup vs baseline: 1.3531x; 1.0572x over previous
#include <cuda_runtime.h>
#include <cuda_bf16.h>
#include <math.h>
#include <stdint.h>

#define QLEN  2048
#define BSZ   2
#define NH    16
#define DH    64
#define DM    1024
#define KLEN  2048
#define RLEN  2048
// 0.125 * log2(e): scores stored in base-2 domain so softmax uses 2^x
#define SCALE_L2E 0.1803368801111244f

// ---------------- scratch (device globals) ----------------------------------
__device__ float g_Qb[(size_t)BSZ * NH * QLEN * DH];   // Q + r_r_bias, (b,n,q,d)
__device__ float g_K [(size_t)BSZ * NH * KLEN * DH];   // (b,n,k,d)
__device__ float g_V [(size_t)BSZ * NH * KLEN * DH];   // (b,n,k,d)
__device__ float g_Rk[(size_t)NH * RLEN * DH];         // (n,r,d)
__device__ float g_AV[(size_t)QLEN * BSZ * DM];        // attn_vec (q,b,n*d)
__device__ float g_negmask[(size_t)BSZ * KLEN];        // 0 or -inf, [b][k]

// ---------------- helpers -----------------------------------------------------
__device__ __forceinline__ uint32_t f2tf(float f) {
    uint32_t u; asm("cvt.rna.tf32.f32 %0, %1;" : "=r"(u) : "f"(f)); return u;
}
__device__ __forceinline__ void mma8(float* c, const uint32_t* a, const uint32_t* b) {
    asm volatile(
        "mma.sync.aligned.m16n8k8.row.col.f32.tf32.tf32.f32 "
        "{%0,%1,%2,%3}, {%4,%5,%6,%7}, {%8,%9}, {%0,%1,%2,%3};"
        : "+f"(c[0]), "+f"(c[1]), "+f"(c[2]), "+f"(c[3])
        : "r"(a[0]), "r"(a[1]), "r"(a[2]), "r"(a[3]), "r"(b[0]), "r"(b[1]));
}
// branch-free 2^t on FMA/ALU pipes. t <= 0 expected; -inf -> ~0.
__device__ __forceinline__ float fexp2(float t) {
    t = fmaxf(t, -126.0f);
    float u = t + 12582912.0f;
    int ki = __float_as_int(u) - 0x4B400000;
    float fk = u - 12582912.0f;
    float f = t - fk;
    float p = 0.0013333558f;
    p = fmaf(p, f, 0.0096181291f);
    p = fmaf(p, f, 0.0555041087f);
    p = fmaf(p, f, 0.2402265069f);
    p = fmaf(p, f, 0.6931471806f);
    p = fmaf(p, f, 1.0f);
    return __int_as_float(__float_as_int(p) + (ki << 23));
}

// ---------------- mask detect + expand (validated) ---------------------------
__global__ void mask_expand_kernel(const unsigned char* __restrict__ m) {
    __shared__ int cnt[4];
    __shared__ int smode;
    if (threadIdx.x < 4) cnt[threadIdx.x] = 0;
    __syncthreads();
    for (int i = threadIdx.x; i < 4096; i += blockDim.x)
        if (m[i]) atomicAdd(&cnt[i & 3], 1);
    __syncthreads();
    if (threadIdx.x == 0) {
        int mode;
        if (cnt[1] == 0 && cnt[2] == 0 && cnt[3] == 0) mode = 0;      // int32
        else if (cnt[0] == 0 && cnt[1] == 0)           mode = 1;      // float32
        else                                           mode = 2;      // bool byte
        smode = mode;
    }
    __syncthreads();
    int mode = smode;
    for (int idx = threadIdx.x; idx < KLEN * BSZ; idx += blockDim.x) {
        bool msk;
        if (mode == 0)      msk = ((const int*)m)[idx] != 0;
        else if (mode == 1) msk = ((const float*)m)[idx] != 0.0f;
        else                msk = m[idx] != 0;
        int k = idx >> 1, b = idx & 1;
        g_negmask[b * KLEN + k] = msk ? -INFINITY : 0.0f;
    }
}

// =============================================================================
// NN TF32 MMA GEMM body (validated round 6)
// =============================================================================
#define NN_TF32_BODY(Aptr, Bptr, Kdim, Ndim, ...)                               \
    __shared__ uint32_t As[128][36];                                            \
    __shared__ uint32_t Bs[32][136];                                            \
    int tid = threadIdx.x;                                                      \
    int row0 = blockIdx.y * 128, col0 = blockIdx.x * 128;                       \
    int wid = tid >> 5, lane = tid & 31, g = lane >> 2, t = lane & 3;           \
    int wm = (wid & 3) * 32, wn = (wid >> 2) * 64;                              \
    (void)lane;                                                                 \
    float c[2][8][4] = {};                                                      \
    float4 pa[4], pb[4];                                                        \
    _Pragma("unroll")                                                           \
    for (int i = 0; i < 4; i++) {                                               \
        int f4 = tid + i * 256;                                                 \
        int rw = f4 >> 3, c4 = (f4 & 7) * 4;                                    \
        pa[i] = *(const float4*)&Aptr[(size_t)(row0 + rw) * Kdim + c4];         \
        int brw = f4 >> 5, bc4 = (f4 & 31) * 4;                                 \
        pb[i] = *(const float4*)&Bptr[(size_t)brw * Ndim + col0 + bc4];         \
    }                                                                           \
    for (int k0c = 0; k0c < Kdim; k0c += 32) {                                  \
        _Pragma("unroll")                                                       \
        for (int i = 0; i < 4; i++) {                                           \
            int f4 = tid + i * 256;                                             \
            int rw = f4 >> 3, c4 = (f4 & 7) * 4;                                \
            *(uint4*)&As[rw][c4] =                                              \
                make_uint4(f2tf(pa[i].x), f2tf(pa[i].y), f2tf(pa[i].z), f2tf(pa[i].w)); \
            int brw = f4 >> 5, bc4 = (f4 & 31) * 4;                             \
            *(uint4*)&Bs[brw][bc4] =                                            \
                make_uint4(f2tf(pb[i].x), f2tf(pb[i].y), f2tf(pb[i].z), f2tf(pb[i].w)); \
        }                                                                       \
        __syncthreads();                                                        \
        if (k0c + 32 < Kdim) {                                                  \
            _Pragma("unroll")                                                   \
            for (int i = 0; i < 4; i++) {                                       \
                int f4 = tid + i * 256;                                         \
                int rw = f4 >> 3, c4 = (f4 & 7) * 4;                            \
                pa[i] = *(const float4*)&Aptr[(size_t)(row0 + rw) * Kdim + k0c + 32 + c4]; \
                int brw = f4 >> 5, bc4 = (f4 & 31) * 4;                         \
                pb[i] = *(const float4*)&Bptr[(size_t)(k0c + 32 + brw) * Ndim + col0 + bc4]; \
            }                                                                   \
        }                                                                       \
        _Pragma("unroll")                                                       \
        for (int k0 = 0; k0 < 32; k0 += 8) {                                    \
            uint32_t a[2][4], b2[8][2];                                         \
            _Pragma("unroll")                                                   \
            for (int mt = 0; mt < 2; mt++) {                                    \
                int r = wm + mt * 16 + g;                                       \
                a[mt][0] = As[r][k0 + t];     a[mt][1] = As[r + 8][k0 + t];     \
                a[mt][2] = As[r][k0 + t + 4]; a[mt][3] = As[r + 8][k0 + t + 4]; \
            }                                                                   \
            _Pragma("unroll")                                                   \
            for (int nt = 0; nt < 8; nt++) {                                    \
                int cn = wn + nt * 8 + g;                                       \
                b2[nt][0] = Bs[k0 + t][cn];                                     \
                b2[nt][1] = Bs[k0 + t + 4][cn];                                 \
            }                                                                   \
            _Pragma("unroll")                                                   \
            for (int mt = 0; mt < 2; mt++)                                      \
                _Pragma("unroll")                                               \
                for (int nt = 0; nt < 8; nt++) mma8(c[mt][nt], a[mt], b2[nt]);  \
        }                                                                       \
        __syncthreads();                                                        \
    }                                                                           \
    __VA_ARGS__

// ---------------- GEMM 1: heads = w @ qkv_w -> Qb/K/V (TF32) -----------------
__global__ __launch_bounds__(256)
void gemm_qkv_kernel(const float* __restrict__ A, const float* __restrict__ B,
                     const float* __restrict__ rbias) {
    NN_TF32_BODY(A, B, 1024, 3072, {
        for (int mt = 0; mt < 2; mt++) {
            for (int rr = 0; rr < 2; rr++) {
                int m = row0 + wm + mt * 16 + g + rr * 8;
                int q = m >> 1;
                int bb = m & 1;
                for (int nt = 0; nt < 8; nt++) {
                    int cc = col0 + wn + nt * 8 + 2 * t;
                    int sec = cc >> 10;
                    int h = (cc & 1023) >> 6;
                    int d = cc & 63;
                    size_t off = ((size_t)(bb * NH + h) * QLEN + q) * DH + d;
                    float vx = c[mt][nt][rr * 2 + 0];
                    float vy = c[mt][nt][rr * 2 + 1];
                    if (sec == 0) {
                        float2 rb = *(const float2*)&rbias[h * 64 + d];
                        float2 v;
                        v.x = vx + rb.x;
                        v.y = vy + rb.y;
                        *(float2*)&g_Qb[off] = v;
                    } else if (sec == 1) {
                        float2 v; v.x = vx; v.y = vy;
                        *(float2*)&g_K[off] = v;
                    } else {
                        float2 v; v.x = vx; v.y = vy;
                        *(float2*)&g_V[off] = v;
                    }
                }
            }
        }
    })
}

// ---------------- GEMM 2: r_head_k = r @ r_net_w -> Rk (TF32) ----------------
__global__ __launch_bounds__(256)
void gemm_rnet_kernel(const float* __restrict__ A, const float* __restrict__ B) {
    NN_TF32_BODY(A, B, 1024, 1024, {
        for (int mt = 0; mt < 2; mt++) {
            for (int rr = 0; rr < 2; rr++) {
                int m = row0 + wm + mt * 16 + g + rr * 8;
                for (int nt = 0; nt < 8; nt++) {
                    int cc = col0 + wn + nt * 8 + 2 * t;
                    int h = cc >> 6;
                    int d = cc & 63;
                    float2 v;
                    v.x = c[mt][nt][rr * 2 + 0];
                    v.y = c[mt][nt][rr * 2 + 1];
                    *(float2*)&g_Rk[((size_t)h * RLEN + m) * DH + d] = v;
                }
            }
        }
    })
}

// ---------------- GEMM 6: output = attn_vec @ o_w (TF32) ---------------------
__global__ __launch_bounds__(256)
void gemm_out_kernel(const float* __restrict__ B, float* __restrict__ out) {
    const float* A = g_AV;
    NN_TF32_BODY(A, B, 1024, 1024, {
        for (int mt = 0; mt < 2; mt++) {
            for (int rr = 0; rr < 2; rr++) {
                int m = row0 + wm + mt * 16 + g + rr * 8;
                for (int nt = 0; nt < 8; nt++) {
                    int cc = col0 + wn + nt * 8 + 2 * t;
                    float2 v;
                    v.x = c[mt][nt][rr * 2 + 0];
                    v.y = c[mt][nt][rr * 2 + 1];
                    *(float2*)&out[(size_t)m * 1024 + cc] = v;
                }
            }
        }
    })
}

// =============================================================================
// Fused score kernel: AC MMA + in-kernel BD band MMAs + epilogue.
// SMEM: BDs[128][260] floats | Qs[128][68] | Ks[128][68] (tf32 words)
// =============================================================================
#define SMEM_STRIDE 68
#define BD_STRIDE 260
#define BD_WORDS (128 * BD_STRIDE)

__global__ __launch_bounds__(256, 1)
void score_fused_kernel(float* __restrict__ cov) {
    extern __shared__ uint32_t sm[];
    float* BDs = (float*)sm;                                   // 128 x 260 floats
    uint32_t (*Qs)[SMEM_STRIDE] = (uint32_t(*)[SMEM_STRIDE])(sm + BD_WORDS);
    uint32_t (*Ks)[SMEM_STRIDE] = (uint32_t(*)[SMEM_STRIDE])(sm + BD_WORDS + 128 * SMEM_STRIDE);

    int z = blockIdx.z;
    int b = z >> 4;
    int n = z & (NH - 1);
    const float* Qp  = g_Qb + (size_t)z * QLEN * DH;
    const float* Kp  = g_K  + (size_t)z * KLEN * DH;
    const float* Rkn = g_Rk + (size_t)n * RLEN * DH;
    int row0 = blockIdx.y * 128, col0 = blockIdx.x * 128;
    int tid = threadIdx.x;
    int wid = tid >> 5, lane = tid & 31, g = lane >> 2, t = lane & 3;
    int wm = (wid & 3) * 32, wn = (wid >> 2) * 64;

    // ---- phase 1: load Q, K; AC MMA ----
#pragma unroll
    for (int i = 0; i < 8; i++) {
        int f4 = tid + i * 256;
        int rw = f4 >> 4, c4 = (f4 & 15) * 4;
        float4 qa = *(const float4*)&Qp[(size_t)(row0 + rw) * DH + c4];
        float4 kb = *(const float4*)&Kp[(size_t)(col0 + rw) * DH + c4];
        *(uint4*)&Qs[rw][c4] = make_uint4(f2tf(qa.x), f2tf(qa.y), f2tf(qa.z), f2tf(qa.w));
        *(uint4*)&Ks[rw][c4] = make_uint4(f2tf(kb.x), f2tf(kb.y), f2tf(kb.z), f2tf(kb.w));
    }
    __syncthreads();
    float c[2][8][4] = {};
#pragma unroll
    for (int k0 = 0; k0 < 64; k0 += 8) {
        uint32_t a[2][4], b2[8][2];
#pragma unroll
        for (int mt = 0; mt < 2; mt++) {
            int r = wm + mt * 16 + g;
            a[mt][0] = Qs[r][k0 + t];     a[mt][1] = Qs[r + 8][k0 + t];
            a[mt][2] = Qs[r][k0 + t + 4]; a[mt][3] = Qs[r + 8][k0 + t + 4];
        }
#pragma unroll
        for (int nt = 0; nt < 8; nt++) {
            int r = wn + nt * 8 + g;
            b2[nt][0] = Ks[r][k0 + t];
            b2[nt][1] = Ks[r][k0 + t + 4];
        }
#pragma unroll
        for (int mt = 0; mt < 2; mt++)
#pragma unroll
            for (int nt = 0; nt < 8; nt++) mma8(c[mt][nt], a[mt], b2[nt]);
    }
    __syncthreads();   // AC done; Qs/Ks reusable

    // ---- band parameters ----
    int below = (col0 < row0);
    int diag  = (col0 == row0);
    int d0 = col0 - row0;
    // half A
    int qoffA   = (below || diag) ? 0 : 1;
    int rstartA = (below || diag) ? (1920 + d0) : (d0 - 129);
    // half B
    int qoffB   = below ? 0 : 1;
    int rstartB = below ? (1920 + d0 + 128) : (diag ? -1 : (d0 - 129 + 128));

    int curQoff = 0;
#pragma unroll 1
    for (int half = 0; half < 2; half++) {
        int qoff   = half ? qoffB : qoffA;
        int rstart = half ? rstartB : rstartA;
        // reload Q with +1 offset if needed
        if (qoff != curQoff) {
#pragma unroll
            for (int i = 0; i < 8; i++) {
                int f4 = tid + i * 256;
                int rw = f4 >> 4, c4 = (f4 & 15) * 4;
                int qr = row0 + rw + qoff; if (qr > 2047) qr = 2047;
                float4 qa = *(const float4*)&Qp[(size_t)qr * DH + c4];
                *(uint4*)&Qs[rw][c4] = make_uint4(f2tf(qa.x), f2tf(qa.y), f2tf(qa.z), f2tf(qa.w));
            }
            curQoff = qoff;
        }
        // load Rk band rows (clamped) into Ks
#pragma unroll
        for (int i = 0; i < 8; i++) {
            int f4 = tid + i * 256;
            int rw = f4 >> 4, c4 = (f4 & 15) * 4;
            int rr_ = rstart + rw; if (rr_ < 0) rr_ = 0; if (rr_ > 2047) rr_ = 2047;
            float4 kb = *(const float4*)&Rkn[(size_t)rr_ * DH + c4];
            *(uint4*)&Ks[rw][c4] = make_uint4(f2tf(kb.x), f2tf(kb.y), f2tf(kb.z), f2tf(kb.w));
        }
        __syncthreads();
        float c2[2][8][4] = {};
#pragma unroll
        for (int k0 = 0; k0 < 64; k0 += 8) {
            uint32_t a[2][4], b2[8][2];
#pragma unroll
            for (int mt = 0; mt < 2; mt++) {
                int r = wm + mt * 16 + g;
                a[mt][0] = Qs[r][k0 + t];     a[mt][1] = Qs[r + 8][k0 + t];
                a[mt][2] = Qs[r][k0 + t + 4]; a[mt][3] = Qs[r + 8][k0 + t + 4];
            }
#pragma unroll
            for (int nt = 0; nt < 8; nt++) {
                int r = wn + nt * 8 + g;
                b2[nt][0] = Ks[r][k0 + t];
                b2[nt][1] = Ks[r][k0 + t + 4];
            }
#pragma unroll
            for (int mt = 0; mt < 2; mt++)
#pragma unroll
                for (int nt = 0; nt < 8; nt++) mma8(c2[mt][nt], a[mt], b2[nt]);
        }
        // stage raw half into BDs columns [half*128, half*128+128)
#pragma unroll
        for (int mt = 0; mt < 2; mt++)
#pragma unroll
            for (int nt = 0; nt < 8; nt++)
#pragma unroll
                for (int rr = 0; rr < 2; rr++) {
                    int r = wm + mt * 16 + g + rr * 8;
                    int ccol = half * 128 + wn + nt * 8 + 2 * t;
                    float2 v;
                    v.x = c2[mt][nt][rr * 2 + 0];
                    v.y = c2[mt][nt][rr * 2 + 1];
                    *(float2*)&BDs[r * BD_STRIDE + ccol] = v;
                }
        __syncthreads();
    }

    // ---- epilogue: s = (AC + BDs[qi][127+ki-qi]) * scale + negmask ----
    const float* neg = g_negmask + (size_t)b * KLEN;
    float* Cz = cov + (size_t)z * QLEN * KLEN;
#pragma unroll
    for (int mt = 0; mt < 2; mt++) {
        int qi0 = wm + mt * 16 + g;
#pragma unroll
        for (int nt = 0; nt < 8; nt++) {
            int kloc = wn + nt * 8 + 2 * t;
            int kb = col0 + kloc;
            float2 ng = *(const float2*)&neg[kb];
#pragma unroll
            for (int rr = 0; rr < 2; rr++) {
                int qi = qi0 + rr * 8;
                int q = row0 + qi;
                int jj = 127 + kloc - qi;
                float bdx = (kb     == q + 1) ? 0.0f : BDs[qi * BD_STRIDE + jj];
                float bdy = (kb + 1 == q + 1) ? 0.0f : BDs[qi * BD_STRIDE + jj + 1];
                float2 s;
                s.x = (c[mt][nt][rr * 2 + 0] + bdx) * SCALE_L2E + ng.x;
                s.y = (c[mt][nt][rr * 2 + 1] + bdy) * SCALE_L2E + ng.y;
                *(float2*)&Cz[(size_t)q * KLEN + kb] = s;
            }
        }
    }
}

// ---------------- softmax over k (validated; base-2 domain) ------------------
__global__ __launch_bounds__(256)
void softmax_kernel(float* __restrict__ cov) {
    size_t row = blockIdx.x;
    float* p = cov + row * KLEN;
    int t = threadIdx.x;
    float4 v0 = ((const float4*)p)[t];
    float4 v1 = ((const float4*)p)[t + 256];
    float m = fmaxf(fmaxf(fmaxf(v0.x, v0.y), fmaxf(v0.z, v0.w)),
                    fmaxf(fmaxf(v1.x, v1.y), fmaxf(v1.z, v1.w)));
    __shared__ float sred[8];
#pragma unroll
    for (int o = 16; o; o >>= 1) m = fmaxf(m, __shfl_xor_sync(0xffffffffu, m, o));
    if ((t & 31) == 0) sred[t >> 5] = m;
    __syncthreads();
    if (t < 8) {
        float x = sred[t];
#pragma unroll
        for (int o = 4; o; o >>= 1) x = fmaxf(x, __shfl_xor_sync(0xffu, x, o));
        if (t == 0) sred[0] = x;
    }
    __syncthreads();
    m = sred[0];
    if (m == -INFINITY) {   // fully-masked row -> 0 per reference
        float4 zz = make_float4(0.f, 0.f, 0.f, 0.f);
        ((float4*)p)[t] = zz;
        ((float4*)p)[t + 256] = zz;
        return;
    }
    float e0x = fexp2(v0.x - m), e0y = fexp2(v0.y - m);
    float e0z = fexp2(v0.z - m), e0w = fexp2(v0.w - m);
    float e1x = fexp2(v1.x - m), e1y = fexp2(v1.y - m);
    float e1z = fexp2(v1.z - m), e1w = fexp2(v1.w - m);
    float s = (e0x + e0y) + (e0z + e0w) + (e1x + e1y) + (e1z + e1w);
    __shared__ float ssum[8];
#pragma unroll
    for (int o = 16; o; o >>= 1) s += __shfl_xor_sync(0xffffffffu, s, o);
    if ((t & 31) == 0) ssum[t >> 5] = s;
    __syncthreads();
    if (t < 8) {
        float x = ssum[t];
#pragma unroll
        for (int o = 4; o; o >>= 1) x += __shfl_xor_sync(0xffu, x, o);
        if (t == 0) ssum[0] = x;
    }
    __syncthreads();
    float inv = 1.0f / ssum[0];
    ((float4*)p)[t]       = make_float4(e0x * inv, e0y * inv, e0z * inv, e0w * inv);
    ((float4*)p)[t + 256] = make_float4(e1x * inv, e1y * inv, e1z * inv, e1w * inv);
}

// ---------------- PV: attn_vec = P @ V (TF32 MMA, validated r6) --------------
__global__ __launch_bounds__(256)
void pv_mma_kernel(const float* __restrict__ cov) {
    extern __shared__ uint32_t sm[];
    uint32_t (*Ps)[SMEM_STRIDE] = (uint32_t(*)[SMEM_STRIDE])sm;
    uint32_t (*Vs)[SMEM_STRIDE] = (uint32_t(*)[SMEM_STRIDE])(sm + 128 * SMEM_STRIDE);
    int z = blockIdx.y;
    int b = z >> 4, n = z & (NH - 1);
    const float* P = cov + (size_t)z * QLEN * KLEN;
    const float* Vm = g_V + (size_t)z * KLEN * DH;
    int row0 = blockIdx.x * 128;
    int tid = threadIdx.x;
    int wid = tid >> 5, lane = tid & 31, g = lane >> 2, t = lane & 3;
    int wm = (wid & 3) * 32, wn = (wid >> 2) * 32;
    float c[2][4][4] = {};
    for (int kc = 0; kc < KLEN; kc += 64) {
#pragma unroll
        for (int i = 0; i < 8; i++) {
            int f4 = tid + i * 256;
            int rw = f4 >> 4, c4 = (f4 & 15) * 4;
            float4 v = *(const float4*)&P[(size_t)(row0 + rw) * KLEN + kc + c4];
            *(uint4*)&Ps[rw][c4] = make_uint4(f2tf(v.x), f2tf(v.y), f2tf(v.z), f2tf(v.w));
        }
#pragma unroll
        for (int i = 0; i < 4; i++) {
            int f4 = tid + i * 256;
            int rw = f4 >> 4, c4 = (f4 & 15) * 4;
            float4 v = *(const float4*)&Vm[(size_t)(kc + rw) * DH + c4];
            *(uint4*)&Vs[rw][c4] = make_uint4(f2tf(v.x), f2tf(v.y), f2tf(v.z), f2tf(v.w));
        }
        __syncthreads();
#pragma unroll
        for (int k0 = 0; k0 < 64; k0 += 8) {
            uint32_t a[2][4], b2[4][2];
#pragma unroll
            for (int mt = 0; mt < 2; mt++) {
                int r = wm + mt * 16 + g;
                a[mt][0] = Ps[r][k0 + t];     a[mt][1] = Ps[r + 8][k0 + t];
                a[mt][2] = Ps[r][k0 + t + 4]; a[mt][3] = Ps[r + 8][k0 + t + 4];
            }
#pragma unroll
            for (int nt = 0; nt < 4; nt++) {
                int cn = wn + nt * 8 + g;
                b2[nt][0] = Vs[k0 + t][cn];
                b2[nt][1] = Vs[k0 + t + 4][cn];
            }
#pragma unroll
            for (int mt = 0; mt < 2; mt++)
#pragma unroll
                for (int nt = 0; nt < 4; nt++) mma8(c[mt][nt], a[mt], b2[nt]);
        }
        __syncthreads();
    }
#pragma unroll
    for (int mt = 0; mt < 2; mt++) {
        int q0 = row0 + wm + mt * 16 + g;
#pragma unroll
        for (int nt = 0; nt < 4; nt++) {
            int d = wn + nt * 8 + 2 * t;
#pragma unroll
            for (int rr = 0; rr < 2; rr++) {
                int q = q0 + rr * 8;
                float2 v;
                v.x = c[mt][nt][rr * 2 + 0];
                v.y = c[mt][nt][rr * 2 + 1];
                *(float2*)&g_AV[((size_t)q * BSZ + b) * DM + n * DH + d] = v;
            }
        }
    }
}

// ---------------- launch ------------------------------------------------------
extern "C" void kernel_launch(void* const* d_in, const int* in_sizes, int n_in,
                              void* d_out, int out_size) {
    const float* w       = (const float*)d_in[0];
    const float* r       = (const float*)d_in[1];
    const void*  mask    = d_in[2];
    const float* qkv_w   = (const float*)d_in[3];
    const float* r_net_w = (const float*)d_in[4];
    const float* o_w     = (const float*)d_in[5];
    const float* r_r_bias = (const float*)d_in[7];  // reference bug: r_r_bias for both

    float* out = (float*)d_out;
    float* cov = out + (size_t)QLEN * BSZ * DM;

    const int SMEM_FUSED = (BD_WORDS + 2 * 128 * SMEM_STRIDE) * 4;  // 202752
    const int SMEM_PV    = (128 + 64) * SMEM_STRIDE * 4;            // 52224
    static int attr_done = 0;
    if (!attr_done) {
        cudaFuncSetAttribute(score_fused_kernel, cudaFuncAttributeMaxDynamicSharedMemorySize, SMEM_FUSED);
        cudaFuncSetAttribute(pv_mma_kernel,      cudaFuncAttributeMaxDynamicSharedMemorySize, SMEM_PV);
        attr_done = 1;
    }

    mask_expand_kernel<<<1, 256>>>((const unsigned char*)mask);
    gemm_qkv_kernel<<<dim3(24, 32), 256>>>(w, qkv_w, r_r_bias);
    gemm_rnet_kernel<<<dim3(8, 16), 256>>>(r, r_net_w);
    score_fused_kernel<<<dim3(16, 16, BSZ * NH), 256, SMEM_FUSED>>>(cov);
    softmax_kernel<<<BSZ * NH * QLEN, 256>>>(cov);
    pv_mma_kernel<<<dim3(16, BSZ * NH), 256, SMEM_PV>>>(cov);
    gemm_out_kernel<<<dim3(8, 32), 256>>>(o_w, out);
}

// round 11
// speedup vs baseline: 1.3837x; 1.0226x over previous
#include <cuda_runtime.h>
#include <cuda_bf16.h>
#include <math.h>
#include <stdint.h>

#define QLEN  2048
#define BSZ   2
#define NH    16
#define DH    64
#define DM    1024
#define KLEN  2048
#define RLEN  2048
// 0.125 * log2(e): scores stored in base-2 domain so softmax uses 2^x
#define SCALE_L2E 0.1803368801111244f

// ---------------- scratch (device globals) ----------------------------------
__device__ float g_Qb[(size_t)BSZ * NH * QLEN * DH];   // Q + r_r_bias, (b,n,q,d)
__device__ float g_K [(size_t)BSZ * NH * KLEN * DH];   // (b,n,k,d)
__device__ float g_V [(size_t)BSZ * NH * KLEN * DH];   // (b,n,k,d)
__device__ float g_Rk[(size_t)NH * RLEN * DH];         // (n,r,d)
__device__ float g_AV[(size_t)QLEN * BSZ * DM];        // attn_vec (q,b,n*d)
__device__ float g_negmask[(size_t)BSZ * KLEN];        // 0 or -inf, [b][k]

// ---------------- helpers -----------------------------------------------------
__device__ __forceinline__ uint32_t f2tf(float f) {
    uint32_t u; asm("cvt.rna.tf32.f32 %0, %1;" : "=r"(u) : "f"(f)); return u;
}
__device__ __forceinline__ void mma8(float* c, const uint32_t* a, const uint32_t* b) {
    asm volatile(
        "mma.sync.aligned.m16n8k8.row.col.f32.tf32.tf32.f32 "
        "{%0,%1,%2,%3}, {%4,%5,%6,%7}, {%8,%9}, {%0,%1,%2,%3};"
        : "+f"(c[0]), "+f"(c[1]), "+f"(c[2]), "+f"(c[3])
        : "r"(a[0]), "r"(a[1]), "r"(a[2]), "r"(a[3]), "r"(b[0]), "r"(b[1]));
}
// branch-free 2^t on FMA/ALU pipes. t <= 0 expected; -inf -> ~0.
__device__ __forceinline__ float fexp2(float t) {
    t = fmaxf(t, -126.0f);
    float u = t + 12582912.0f;
    int ki = __float_as_int(u) - 0x4B400000;
    float fk = u - 12582912.0f;
    float f = t - fk;
    float p = 0.0013333558f;
    p = fmaf(p, f, 0.0096181291f);
    p = fmaf(p, f, 0.0555041087f);
    p = fmaf(p, f, 0.2402265069f);
    p = fmaf(p, f, 0.6931471806f);
    p = fmaf(p, f, 1.0f);
    return __int_as_float(__float_as_int(p) + (ki << 23));
}

// ---------------- mask detect + expand (validated) ---------------------------
__global__ void mask_expand_kernel(const unsigned char* __restrict__ m) {
    __shared__ int cnt[4];
    __shared__ int smode;
    if (threadIdx.x < 4) cnt[threadIdx.x] = 0;
    __syncthreads();
    for (int i = threadIdx.x; i < 4096; i += blockDim.x)
        if (m[i]) atomicAdd(&cnt[i & 3], 1);
    __syncthreads();
    if (threadIdx.x == 0) {
        int mode;
        if (cnt[1] == 0 && cnt[2] == 0 && cnt[3] == 0) mode = 0;      // int32
        else if (cnt[0] == 0 && cnt[1] == 0)           mode = 1;      // float32
        else                                           mode = 2;      // bool byte
        smode = mode;
    }
    __syncthreads();
    int mode = smode;
    for (int idx = threadIdx.x; idx < KLEN * BSZ; idx += blockDim.x) {
        bool msk;
        if (mode == 0)      msk = ((const int*)m)[idx] != 0;
        else if (mode == 1) msk = ((const float*)m)[idx] != 0.0f;
        else                msk = m[idx] != 0;
        int k = idx >> 1, b = idx & 1;
        g_negmask[b * KLEN + k] = msk ? -INFINITY : 0.0f;
    }
}

// =============================================================================
// NN TF32 MMA GEMM body (validated round 6)
// =============================================================================
#define NN_TF32_BODY(Aptr, Bptr, Kdim, Ndim, ...)                               \
    __shared__ uint32_t As[128][36];                                            \
    __shared__ uint32_t Bs[32][136];                                            \
    int tid = threadIdx.x;                                                      \
    int row0 = blockIdx.y * 128, col0 = blockIdx.x * 128;                       \
    int wid = tid >> 5, lane = tid & 31, g = lane >> 2, t = lane & 3;           \
    int wm = (wid & 3) * 32, wn = (wid >> 2) * 64;                              \
    (void)lane;                                                                 \
    float c[2][8][4] = {};                                                      \
    float4 pa[4], pb[4];                                                        \
    _Pragma("unroll")                                                           \
    for (int i = 0; i < 4; i++) {                                               \
        int f4 = tid + i * 256;                                                 \
        int rw = f4 >> 3, c4 = (f4 & 7) * 4;                                    \
        pa[i] = *(const float4*)&Aptr[(size_t)(row0 + rw) * Kdim + c4];         \
        int brw = f4 >> 5, bc4 = (f4 & 31) * 4;                                 \
        pb[i] = *(const float4*)&Bptr[(size_t)brw * Ndim + col0 + bc4];         \
    }                                                                           \
    for (int k0c = 0; k0c < Kdim; k0c += 32) {                                  \
        _Pragma("unroll")                                                       \
        for (int i = 0; i < 4; i++) {                                           \
            int f4 = tid + i * 256;                                             \
            int rw = f4 >> 3, c4 = (f4 & 7) * 4;                                \
            *(uint4*)&As[rw][c4] =                                              \
                make_uint4(f2tf(pa[i].x), f2tf(pa[i].y), f2tf(pa[i].z), f2tf(pa[i].w)); \
            int brw = f4 >> 5, bc4 = (f4 & 31) * 4;                             \
            *(uint4*)&Bs[brw][bc4] =                                            \
                make_uint4(f2tf(pb[i].x), f2tf(pb[i].y), f2tf(pb[i].z), f2tf(pb[i].w)); \
        }                                                                       \
        __syncthreads();                                                        \
        if (k0c + 32 < Kdim) {                                                  \
            _Pragma("unroll")                                                   \
            for (int i = 0; i < 4; i++) {                                       \
                int f4 = tid + i * 256;                                         \
                int rw = f4 >> 3, c4 = (f4 & 7) * 4;                            \
                pa[i] = *(const float4*)&Aptr[(size_t)(row0 + rw) * Kdim + k0c + 32 + c4]; \
                int brw = f4 >> 5, bc4 = (f4 & 31) * 4;                         \
                pb[i] = *(const float4*)&Bptr[(size_t)(k0c + 32 + brw) * Ndim + col0 + bc4]; \
            }                                                                   \
        }                                                                       \
        _Pragma("unroll")                                                       \
        for (int k0 = 0; k0 < 32; k0 += 8) {                                    \
            uint32_t a[2][4], b2[8][2];                                         \
            _Pragma("unroll")                                                   \
            for (int mt = 0; mt < 2; mt++) {                                    \
                int r = wm + mt * 16 + g;                                       \
                a[mt][0] = As[r][k0 + t];     a[mt][1] = As[r + 8][k0 + t];     \
                a[mt][2] = As[r][k0 + t + 4]; a[mt][3] = As[r + 8][k0 + t + 4]; \
            }                                                                   \
            _Pragma("unroll")                                                   \
            for (int nt = 0; nt < 8; nt++) {                                    \
                int cn = wn + nt * 8 + g;                                       \
                b2[nt][0] = Bs[k0 + t][cn];                                     \
                b2[nt][1] = Bs[k0 + t + 4][cn];                                 \
            }                                                                   \
            _Pragma("unroll")                                                   \
            for (int mt = 0; mt < 2; mt++)                                      \
                _Pragma("unroll")                                               \
                for (int nt = 0; nt < 8; nt++) mma8(c[mt][nt], a[mt], b2[nt]);  \
        }                                                                       \
        __syncthreads();                                                        \
    }                                                                           \
    __VA_ARGS__

// ---------------- GEMM 1: heads = w @ qkv_w -> Qb/K/V (TF32) -----------------
__global__ __launch_bounds__(256)
void gemm_qkv_kernel(const float* __restrict__ A, const float* __restrict__ B,
                     const float* __restrict__ rbias) {
    NN_TF32_BODY(A, B, 1024, 3072, {
        for (int mt = 0; mt < 2; mt++) {
            for (int rr = 0; rr < 2; rr++) {
                int m = row0 + wm + mt * 16 + g + rr * 8;
                int q = m >> 1;
                int bb = m & 1;
                for (int nt = 0; nt < 8; nt++) {
                    int cc = col0 + wn + nt * 8 + 2 * t;
                    int sec = cc >> 10;
                    int h = (cc & 1023) >> 6;
                    int d = cc & 63;
                    size_t off = ((size_t)(bb * NH + h) * QLEN + q) * DH + d;
                    float vx = c[mt][nt][rr * 2 + 0];
                    float vy = c[mt][nt][rr * 2 + 1];
                    if (sec == 0) {
                        float2 rb = *(const float2*)&rbias[h * 64 + d];
                        float2 v;
                        v.x = vx + rb.x;
                        v.y = vy + rb.y;
                        *(float2*)&g_Qb[off] = v;
                    } else if (sec == 1) {
                        float2 v; v.x = vx; v.y = vy;
                        *(float2*)&g_K[off] = v;
                    } else {
                        float2 v; v.x = vx; v.y = vy;
                        *(float2*)&g_V[off] = v;
                    }
                }
            }
        }
    })
}

// ---------------- GEMM 2: r_head_k = r @ r_net_w -> Rk (TF32) ----------------
__global__ __launch_bounds__(256)
void gemm_rnet_kernel(const float* __restrict__ A, const float* __restrict__ B) {
    NN_TF32_BODY(A, B, 1024, 1024, {
        for (int mt = 0; mt < 2; mt++) {
            for (int rr = 0; rr < 2; rr++) {
                int m = row0 + wm + mt * 16 + g + rr * 8;
                for (int nt = 0; nt < 8; nt++) {
                    int cc = col0 + wn + nt * 8 + 2 * t;
                    int h = cc >> 6;
                    int d = cc & 63;
                    float2 v;
                    v.x = c[mt][nt][rr * 2 + 0];
                    v.y = c[mt][nt][rr * 2 + 1];
                    *(float2*)&g_Rk[((size_t)h * RLEN + m) * DH + d] = v;
                }
            }
        }
    })
}

// ---------------- GEMM 6: output = attn_vec @ o_w (TF32) ---------------------
__global__ __launch_bounds__(256)
void gemm_out_kernel(const float* __restrict__ B, float* __restrict__ out) {
    const float* A = g_AV;
    NN_TF32_BODY(A, B, 1024, 1024, {
        for (int mt = 0; mt < 2; mt++) {
            for (int rr = 0; rr < 2; rr++) {
                int m = row0 + wm + mt * 16 + g + rr * 8;
                for (int nt = 0; nt < 8; nt++) {
                    int cc = col0 + wn + nt * 8 + 2 * t;
                    float2 v;
                    v.x = c[mt][nt][rr * 2 + 0];
                    v.y = c[mt][nt][rr * 2 + 1];
                    *(float2*)&out[(size_t)m * 1024 + cc] = v;
                }
            }
        }
    })
}

// =============================================================================
// Fused score kernel, 512 threads / 16 warps (warp tile 32x32).
// SMEM: BDs[128][260] floats | Qs[128][68] | Ks[128][68] (tf32 words)
// =============================================================================
#define SMEM_STRIDE 68
#define BD_STRIDE 260
#define BD_WORDS (128 * BD_STRIDE)

__global__ __launch_bounds__(512, 1)
void score_fused_kernel(float* __restrict__ cov) {
    extern __shared__ uint32_t sm[];
    float* BDs = (float*)sm;                                   // 128 x 260 floats
    uint32_t (*Qs)[SMEM_STRIDE] = (uint32_t(*)[SMEM_STRIDE])(sm + BD_WORDS);
    uint32_t (*Ks)[SMEM_STRIDE] = (uint32_t(*)[SMEM_STRIDE])(sm + BD_WORDS + 128 * SMEM_STRIDE);

    int z = blockIdx.z;
    int b = z >> 4;
    int n = z & (NH - 1);
    const float* Qp  = g_Qb + (size_t)z * QLEN * DH;
    const float* Kp  = g_K  + (size_t)z * KLEN * DH;
    const float* Rkn = g_Rk + (size_t)n * RLEN * DH;
    int row0 = blockIdx.y * 128, col0 = blockIdx.x * 128;
    int tid = threadIdx.x;
    int wid = tid >> 5, lane = tid & 31, g = lane >> 2, t = lane & 3;
    int wm = (wid & 3) * 32, wn = (wid >> 2) * 32;   // 4x4 warp grid, 32x32 tiles

    // ---- phase 1: load Q, K; AC MMA ----
#pragma unroll
    for (int i = 0; i < 4; i++) {
        int f4 = tid + i * 512;
        int rw = f4 >> 4, c4 = (f4 & 15) * 4;
        float4 qa = *(const float4*)&Qp[(size_t)(row0 + rw) * DH + c4];
        float4 kb = *(const float4*)&Kp[(size_t)(col0 + rw) * DH + c4];
        *(uint4*)&Qs[rw][c4] = make_uint4(f2tf(qa.x), f2tf(qa.y), f2tf(qa.z), f2tf(qa.w));
        *(uint4*)&Ks[rw][c4] = make_uint4(f2tf(kb.x), f2tf(kb.y), f2tf(kb.z), f2tf(kb.w));
    }
    __syncthreads();
    float c[2][4][4] = {};
#pragma unroll
    for (int k0 = 0; k0 < 64; k0 += 8) {
        uint32_t a[2][4], b2[4][2];
#pragma unroll
        for (int mt = 0; mt < 2; mt++) {
            int r = wm + mt * 16 + g;
            a[mt][0] = Qs[r][k0 + t];     a[mt][1] = Qs[r + 8][k0 + t];
            a[mt][2] = Qs[r][k0 + t + 4]; a[mt][3] = Qs[r + 8][k0 + t + 4];
        }
#pragma unroll
        for (int nt = 0; nt < 4; nt++) {
            int r = wn + nt * 8 + g;
            b2[nt][0] = Ks[r][k0 + t];
            b2[nt][1] = Ks[r][k0 + t + 4];
        }
#pragma unroll
        for (int mt = 0; mt < 2; mt++)
#pragma unroll
            for (int nt = 0; nt < 4; nt++) mma8(c[mt][nt], a[mt], b2[nt]);
    }
    __syncthreads();   // AC done; Qs/Ks reusable

    // ---- band parameters (validated round 10) ----
    int below = (col0 < row0);
    int diag  = (col0 == row0);
    int d0 = col0 - row0;
    int qoffA   = (below || diag) ? 0 : 1;
    int rstartA = (below || diag) ? (1920 + d0) : (d0 - 129);
    int qoffB   = below ? 0 : 1;
    int rstartB = below ? (1920 + d0 + 128) : (diag ? -1 : (d0 - 129 + 128));

    int curQoff = 0;
#pragma unroll 1
    for (int half = 0; half < 2; half++) {
        int qoff   = half ? qoffB : qoffA;
        int rstart = half ? rstartB : rstartA;
        if (qoff != curQoff) {
#pragma unroll
            for (int i = 0; i < 4; i++) {
                int f4 = tid + i * 512;
                int rw = f4 >> 4, c4 = (f4 & 15) * 4;
                int qr = row0 + rw + qoff; if (qr > 2047) qr = 2047;
                float4 qa = *(const float4*)&Qp[(size_t)qr * DH + c4];
                *(uint4*)&Qs[rw][c4] = make_uint4(f2tf(qa.x), f2tf(qa.y), f2tf(qa.z), f2tf(qa.w));
            }
            curQoff = qoff;
        }
#pragma unroll
        for (int i = 0; i < 4; i++) {
            int f4 = tid + i * 512;
            int rw = f4 >> 4, c4 = (f4 & 15) * 4;
            int rr_ = rstart + rw; if (rr_ < 0) rr_ = 0; if (rr_ > 2047) rr_ = 2047;
            float4 kb = *(const float4*)&Rkn[(size_t)rr_ * DH + c4];
            *(uint4*)&Ks[rw][c4] = make_uint4(f2tf(kb.x), f2tf(kb.y), f2tf(kb.z), f2tf(kb.w));
        }
        __syncthreads();
        float c2[2][4][4] = {};
#pragma unroll
        for (int k0 = 0; k0 < 64; k0 += 8) {
            uint32_t a[2][4], b2[4][2];
#pragma unroll
            for (int mt = 0; mt < 2; mt++) {
                int r = wm + mt * 16 + g;
                a[mt][0] = Qs[r][k0 + t];     a[mt][1] = Qs[r + 8][k0 + t];
                a[mt][2] = Qs[r][k0 + t + 4]; a[mt][3] = Qs[r + 8][k0 + t + 4];
            }
#pragma unroll
            for (int nt = 0; nt < 4; nt++) {
                int r = wn + nt * 8 + g;
                b2[nt][0] = Ks[r][k0 + t];
                b2[nt][1] = Ks[r][k0 + t + 4];
            }
#pragma unroll
            for (int mt = 0; mt < 2; mt++)
#pragma unroll
                for (int nt = 0; nt < 4; nt++) mma8(c2[mt][nt], a[mt], b2[nt]);
        }
        // stage raw half into BDs columns [half*128, half*128+128)
#pragma unroll
        for (int mt = 0; mt < 2; mt++)
#pragma unroll
            for (int nt = 0; nt < 4; nt++)
#pragma unroll
                for (int rr = 0; rr < 2; rr++) {
                    int r = wm + mt * 16 + g + rr * 8;
                    int ccol = half * 128 + wn + nt * 8 + 2 * t;
                    float2 v;
                    v.x = c2[mt][nt][rr * 2 + 0];
                    v.y = c2[mt][nt][rr * 2 + 1];
                    *(float2*)&BDs[r * BD_STRIDE + ccol] = v;
                }
        __syncthreads();
    }

    // ---- epilogue: s = (AC + BDs[qi][127+ki-qi]) * scale + negmask ----
    const float* neg = g_negmask + (size_t)b * KLEN;
    float* Cz = cov + (size_t)z * QLEN * KLEN;
#pragma unroll
    for (int mt = 0; mt < 2; mt++) {
        int qi0 = wm + mt * 16 + g;
#pragma unroll
        for (int nt = 0; nt < 4; nt++) {
            int kloc = wn + nt * 8 + 2 * t;
            int kb = col0 + kloc;
            float2 ng = *(const float2*)&neg[kb];
#pragma unroll
            for (int rr = 0; rr < 2; rr++) {
                int qi = qi0 + rr * 8;
                int q = row0 + qi;
                int jj = 127 + kloc - qi;
                float bdx = (kb     == q + 1) ? 0.0f : BDs[qi * BD_STRIDE + jj];
                float bdy = (kb + 1 == q + 1) ? 0.0f : BDs[qi * BD_STRIDE + jj + 1];
                float2 s;
                s.x = (c[mt][nt][rr * 2 + 0] + bdx) * SCALE_L2E + ng.x;
                s.y = (c[mt][nt][rr * 2 + 1] + bdy) * SCALE_L2E + ng.y;
                *(float2*)&Cz[(size_t)q * KLEN + kb] = s;
            }
        }
    }
}

// ---------------- softmax over k (validated; base-2 domain) ------------------
__global__ __launch_bounds__(256)
void softmax_kernel(float* __restrict__ cov) {
    size_t row = blockIdx.x;
    float* p = cov + row * KLEN;
    int t = threadIdx.x;
    float4 v0 = ((const float4*)p)[t];
    float4 v1 = ((const float4*)p)[t + 256];
    float m = fmaxf(fmaxf(fmaxf(v0.x, v0.y), fmaxf(v0.z, v0.w)),
                    fmaxf(fmaxf(v1.x, v1.y), fmaxf(v1.z, v1.w)));
    __shared__ float sred[8];
#pragma unroll
    for (int o = 16; o; o >>= 1) m = fmaxf(m, __shfl_xor_sync(0xffffffffu, m, o));
    if ((t & 31) == 0) sred[t >> 5] = m;
    __syncthreads();
    if (t < 8) {
        float x = sred[t];
#pragma unroll
        for (int o = 4; o; o >>= 1) x = fmaxf(x, __shfl_xor_sync(0xffu, x, o));
        if (t == 0) sred[0] = x;
    }
    __syncthreads();
    m = sred[0];
    if (m == -INFINITY) {   // fully-masked row -> 0 per reference
        float4 zz = make_float4(0.f, 0.f, 0.f, 0.f);
        ((float4*)p)[t] = zz;
        ((float4*)p)[t + 256] = zz;
        return;
    }
    float e0x = fexp2(v0.x - m), e0y = fexp2(v0.y - m);
    float e0z = fexp2(v0.z - m), e0w = fexp2(v0.w - m);
    float e1x = fexp2(v1.x - m), e1y = fexp2(v1.y - m);
    float e1z = fexp2(v1.z - m), e1w = fexp2(v1.w - m);
    float s = (e0x + e0y) + (e0z + e0w) + (e1x + e1y) + (e1z + e1w);
    __shared__ float ssum[8];
#pragma unroll
    for (int o = 16; o; o >>= 1) s += __shfl_xor_sync(0xffffffffu, s, o);
    if ((t & 31) == 0) ssum[t >> 5] = s;
    __syncthreads();
    if (t < 8) {
        float x = ssum[t];
#pragma unroll
        for (int o = 4; o; o >>= 1) x += __shfl_xor_sync(0xffu, x, o);
        if (t == 0) ssum[0] = x;
    }
    __syncthreads();
    float inv = 1.0f / ssum[0];
    ((float4*)p)[t]       = make_float4(e0x * inv, e0y * inv, e0z * inv, e0w * inv);
    ((float4*)p)[t + 256] = make_float4(e1x * inv, e1y * inv, e1z * inv, e1w * inv);
}

// ---------------- PV: attn_vec = P @ V (TF32 MMA, validated r6) --------------
__global__ __launch_bounds__(256)
void pv_mma_kernel(const float* __restrict__ cov) {
    extern __shared__ uint32_t sm[];
    uint32_t (*Ps)[SMEM_STRIDE] = (uint32_t(*)[SMEM_STRIDE])sm;
    uint32_t (*Vs)[SMEM_STRIDE] = (uint32_t(*)[SMEM_STRIDE])(sm + 128 * SMEM_STRIDE);
    int z = blockIdx.y;
    int b = z >> 4, n = z & (NH - 1);
    const float* P = cov + (size_t)z * QLEN * KLEN;
    const float* Vm = g_V + (size_t)z * KLEN * DH;
    int row0 = blockIdx.x * 128;
    int tid = threadIdx.x;
    int wid = tid >> 5, lane = tid & 31, g = lane >> 2, t = lane & 3;
    int wm = (wid & 3) * 32, wn = (wid >> 2) * 32;
    float c[2][4][4] = {};
    for (int kc = 0; kc < KLEN; kc += 64) {
#pragma unroll
        for (int i = 0; i < 8; i++) {
            int f4 = tid + i * 256;
            int rw = f4 >> 4, c4 = (f4 & 15) * 4;
            float4 v = *(const float4*)&P[(size_t)(row0 + rw) * KLEN + kc + c4];
            *(uint4*)&Ps[rw][c4] = make_uint4(f2tf(v.x), f2tf(v.y), f2tf(v.z), f2tf(v.w));
        }
#pragma unroll
        for (int i = 0; i < 4; i++) {
            int f4 = tid + i * 256;
            int rw = f4 >> 4, c4 = (f4 & 15) * 4;
            float4 v = *(const float4*)&Vm[(size_t)(kc + rw) * DH + c4];
            *(uint4*)&Vs[rw][c4] = make_uint4(f2tf(v.x), f2tf(v.y), f2tf(v.z), f2tf(v.w));
        }
        __syncthreads();
#pragma unroll
        for (int k0 = 0; k0 < 64; k0 += 8) {
            uint32_t a[2][4], b2[4][2];
#pragma unroll
            for (int mt = 0; mt < 2; mt++) {
                int r = wm + mt * 16 + g;
                a[mt][0] = Ps[r][k0 + t];     a[mt][1] = Ps[r + 8][k0 + t];
                a[mt][2] = Ps[r][k0 + t + 4]; a[mt][3] = Ps[r + 8][k0 + t + 4];
            }
#pragma unroll
            for (int nt = 0; nt < 4; nt++) {
                int cn = wn + nt * 8 + g;
                b2[nt][0] = Vs[k0 + t][cn];
                b2[nt][1] = Vs[k0 + t + 4][cn];
            }
#pragma unroll
            for (int mt = 0; mt < 2; mt++)
#pragma unroll
                for (int nt = 0; nt < 4; nt++) mma8(c[mt][nt], a[mt], b2[nt]);
        }
        __syncthreads();
    }
#pragma unroll
    for (int mt = 0; mt < 2; mt++) {
        int q0 = row0 + wm + mt * 16 + g;
#pragma unroll
        for (int nt = 0; nt < 4; nt++) {
            int d = wn + nt * 8 + 2 * t;
#pragma unroll
            for (int rr = 0; rr < 2; rr++) {
                int q = q0 + rr * 8;
                float2 v;
                v.x = c[mt][nt][rr * 2 + 0];
                v.y = c[mt][nt][rr * 2 + 1];
                *(float2*)&g_AV[((size_t)q * BSZ + b) * DM + n * DH + d] = v;
            }
        }
    }
}

// ---------------- launch ------------------------------------------------------
extern "C" void kernel_launch(void* const* d_in, const int* in_sizes, int n_in,
                              void* d_out, int out_size) {
    const float* w       = (const float*)d_in[0];
    const float* r       = (const float*)d_in[1];
    const void*  mask    = d_in[2];
    const float* qkv_w   = (const float*)d_in[3];
    const float* r_net_w = (const float*)d_in[4];
    const float* o_w     = (const float*)d_in[5];
    const float* r_r_bias = (const float*)d_in[7];  // reference bug: r_r_bias for both

    float* out = (float*)d_out;
    float* cov = out + (size_t)QLEN * BSZ * DM;

    const int SMEM_FUSED = (BD_WORDS + 2 * 128 * SMEM_STRIDE) * 4;  // 202752
    const int SMEM_PV    = (128 + 64) * SMEM_STRIDE * 4;            // 52224
    static int attr_done = 0;
    if (!attr_done) {
        cudaFuncSetAttribute(score_fused_kernel, cudaFuncAttributeMaxDynamicSharedMemorySize, SMEM_FUSED);
        cudaFuncSetAttribute(pv_mma_kernel,      cudaFuncAttributeMaxDynamicSharedMemorySize, SMEM_PV);
        attr_done = 1;
    }

    mask_expand_kernel<<<1, 256>>>((const unsigned char*)mask);
    gemm_qkv_kernel<<<dim3(24, 32), 256>>>(w, qkv_w, r_r_bias);
    gemm_rnet_kernel<<<dim3(8, 16), 256>>>(r, r_net_w);
    score_fused_kernel<<<dim3(16, 16, BSZ * NH), 512, SMEM_FUSED>>>(cov);
    softmax_kernel<<<BSZ * NH * QLEN, 256>>>(cov);
    pv_mma_kernel<<<dim3(16, BSZ * NH), 256, SMEM_PV>>>(cov);
    gemm_out_kernel<<<dim3(8, 32), 256>>>(o_w, out);
}